// round 5
// baseline (speedup 1.0000x reference)
#include <cuda_runtime.h>
#include <cuda_bf16.h>
#include <stdint.h>

// ---------------------------------------------------------------------------
// GCN 2-layer, CSR pull-based aggregation + tf32 tensor-core GEMMs.
//   dinv = (1 + indeg)^-1/2
//   h1   = x @ W1                       (raw, no scaling)
//   a1[i]= b1 + dinv[i]*( h1[i]*dinv[i] + sum_{e: dst=i} h1[src]*dinv[src] )
//   h2   = a1 @ W2
//   out[i]= b2 + dinv[i]*( h2[i]*dinv[i] + sum h2[src]*dinv[src] )
// GEMM1 is launch #4 (ncu capture slot).
// ---------------------------------------------------------------------------

#define MAXN 100352
#define MAXE 1048576
#define MAXF 512

__device__ float g_dinv[MAXN];
__device__ float g_h[(size_t)MAXN * MAXF];
__device__ float g_agg[(size_t)MAXN * MAXF];
__device__ int   g_cnt[MAXN];
__device__ int   g_rowp[MAXN + 1];
__device__ int   g_cur[MAXN];
__device__ int   g_col[MAXE];
__device__ int   g_bsum[1025];
__device__ int   g_is64;

// ---------------------------------------------------------------------------
__device__ __forceinline__ long long edge_at(const void* ei, long long idx, int is64) {
    if (is64) return ((const long long*)ei)[idx];
    return (long long)((const int*)ei)[idx];
}

__global__ void k_detect(const void* ei, long long nelem, int n) {
    if (threadIdx.x != 0 || blockIdx.x != 0) return;
    const long long* p = (const long long*)ei;
    long long m = 64;
    if (m > nelem / 2) m = nelem / 2;
    int is64 = 1;
    for (long long i = 0; i < m; i++) {
        long long v = p[i];
        if (v < 0 || v >= (long long)n) { is64 = 0; break; }
    }
    g_is64 = is64;
}

__global__ void k_zero_cnt(int* cnt, int n) {
    int i = blockIdx.x * blockDim.x + threadIdx.x;
    if (i < n) cnt[i] = 0;
}

__global__ void k_hist(const void* __restrict__ ei, long long E, int* __restrict__ cnt) {
    long long i = (long long)blockIdx.x * blockDim.x + threadIdx.x;
    if (i >= E) return;
    int d = (int)edge_at(ei, E + i, g_is64);
    atomicAdd(&cnt[d], 1);
}

// -------- multi-block exclusive scan --------
__global__ void k_scan_blk(const int* __restrict__ cnt, int* __restrict__ rowp,
                           int* __restrict__ bsum, int n) {
    __shared__ int warpsum[32];
    const int t = threadIdx.x;                 // 1024
    const int lane = t & 31, w = t >> 5;
    int i = blockIdx.x * 1024 + t;
    int v = (i < n) ? cnt[i] : 0;
    int x = v;
#pragma unroll
    for (int off = 1; off < 32; off <<= 1) {
        int y = __shfl_up_sync(0xFFFFFFFFu, x, off);
        if (lane >= off) x += y;
    }
    if (lane == 31) warpsum[w] = x;
    __syncthreads();
    if (w == 0) {
        int s = warpsum[lane];
#pragma unroll
        for (int off = 1; off < 32; off <<= 1) {
            int y = __shfl_up_sync(0xFFFFFFFFu, s, off);
            if (lane >= off) s += y;
        }
        warpsum[lane] = s;
    }
    __syncthreads();
    int wpre = (w > 0) ? warpsum[w - 1] : 0;
    if (i < n) rowp[i] = x - v + wpre;
    if (t == 1023) bsum[blockIdx.x] = wpre + x;
}

__global__ void k_scan_top(int* __restrict__ bsum, int nb) {
    __shared__ int warpsum[32];
    const int t = threadIdx.x;                 // 1024 (nb <= 1024)
    const int lane = t & 31, w = t >> 5;
    int v = (t < nb) ? bsum[t] : 0;
    int x = v;
#pragma unroll
    for (int off = 1; off < 32; off <<= 1) {
        int y = __shfl_up_sync(0xFFFFFFFFu, x, off);
        if (lane >= off) x += y;
    }
    if (lane == 31) warpsum[w] = x;
    __syncthreads();
    if (w == 0) {
        int s = warpsum[lane];
#pragma unroll
        for (int off = 1; off < 32; off <<= 1) {
            int y = __shfl_up_sync(0xFFFFFFFFu, s, off);
            if (lane >= off) s += y;
        }
        warpsum[lane] = s;
    }
    __syncthreads();
    int wpre = (w > 0) ? warpsum[w - 1] : 0;
    if (t < nb) bsum[t] = x - v + wpre;
    if (t == 1023) bsum[nb] = warpsum[31];
}

__global__ void k_scan_add(int* __restrict__ rowp, const int* __restrict__ bsum,
                           int n, int nb) {
    int i = blockIdx.x * blockDim.x + threadIdx.x;
    if (i < n) rowp[i] += bsum[i >> 10];
    if (i == n) rowp[n] = bsum[nb];
}

__global__ void k_dinv_cursor(const int* __restrict__ cnt, const int* __restrict__ rowp,
                              float* __restrict__ dinv, int* __restrict__ cur, int n) {
    int i = blockIdx.x * blockDim.x + threadIdx.x;
    if (i >= n) return;
    dinv[i] = rsqrtf((float)cnt[i] + 1.0f);
    cur[i]  = rowp[i];
}

__global__ void k_scatter(const void* __restrict__ ei, long long E,
                          int* __restrict__ cur, int* __restrict__ colA) {
    long long i = (long long)blockIdx.x * blockDim.x + threadIdx.x;
    if (i >= E) return;
    int is64 = g_is64;
    int s = (int)edge_at(ei, i, is64);
    int d = (int)edge_at(ei, E + i, is64);
    int pos = atomicAdd(&cur[d], 1);
    colA[pos] = s;
}

// ---------------------------------------------------------------------------
__device__ __forceinline__ uint32_t f2tf(float x) {
    uint32_t u;
    asm("cvt.rna.tf32.f32 %0, %1;" : "=r"(u) : "f"(x));
    return u;
}

// ---------------------------------------------------------------------------
// GEMM1: 128x256 block tile, BK=16, 256 threads (8 warps, 2x4), warp 64x64.
// H = A @ B (raw). Requires N % 256 == 0, K % 16 == 0. M guarded.
// ---------------------------------------------------------------------------
#define G1_SMEM ((2*16*136 + 2*16*260) * 4)
#define AS(b,k,m) Asb[(((b)*16 + (k)) * 136) + (m)]
#define BS(b,k,nn) Bsb[(((b)*16 + (k)) * 260) + (nn)]

__global__ __launch_bounds__(256, 1)
void k_gemm256(const float* __restrict__ A, const float* __restrict__ B,
               float* __restrict__ H, int M, int N, int K)
{
    extern __shared__ uint32_t smem_u[];
    uint32_t* Asb = smem_u;
    uint32_t* Bsb = smem_u + 2 * 16 * 136;

    const int t    = threadIdx.x;
    const int lane = t & 31;
    const int wid  = t >> 5;
    const int wm   = wid >> 2;
    const int wn   = wid & 3;
    const int g    = lane >> 2;
    const int c    = lane & 3;
    const int m0   = blockIdx.y * 128;
    const int n0   = blockIdx.x * 256;

    const int arow = t >> 1;
    const int ak8  = (t & 1) * 8;
    const int bkr  = t >> 6;
    const int bn4  = t & 63;

    float acc[4][8][4];
#pragma unroll
    for (int i = 0; i < 4; i++)
#pragma unroll
        for (int j = 0; j < 8; j++)
#pragma unroll
            for (int q = 0; q < 4; q++) acc[i][j][q] = 0.0f;

    const int nt = K / 16;
    float4 ra[2], rb[4];

    {
        bool mv = (m0 + arow < M);
        ra[0] = mv ? *(const float4*)&A[(size_t)(m0 + arow) * K + ak8]     : make_float4(0,0,0,0);
        ra[1] = mv ? *(const float4*)&A[(size_t)(m0 + arow) * K + ak8 + 4] : make_float4(0,0,0,0);
#pragma unroll
        for (int i = 0; i < 4; i++)
            rb[i] = *(const float4*)&B[(size_t)(bkr + i * 4) * N + n0 + bn4 * 4];
    }
    {
        const float* rap = (const float*)ra;
#pragma unroll
        for (int j = 0; j < 8; j++) AS(0, ak8 + j, arow) = f2tf(rap[j]);
#pragma unroll
        for (int i = 0; i < 4; i++) {
            int kr = bkr + i * 4;
            BS(0, kr, bn4 * 4 + 0) = f2tf(rb[i].x);
            BS(0, kr, bn4 * 4 + 1) = f2tf(rb[i].y);
            BS(0, kr, bn4 * 4 + 2) = f2tf(rb[i].z);
            BS(0, kr, bn4 * 4 + 3) = f2tf(rb[i].w);
        }
    }

    for (int tt = 0; tt < nt; tt++) {
        __syncthreads();
        const int buf = tt & 1;

        if (tt + 1 < nt) {
            int k0 = (tt + 1) * 16;
            bool mv = (m0 + arow < M);
            ra[0] = mv ? *(const float4*)&A[(size_t)(m0 + arow) * K + k0 + ak8]     : make_float4(0,0,0,0);
            ra[1] = mv ? *(const float4*)&A[(size_t)(m0 + arow) * K + k0 + ak8 + 4] : make_float4(0,0,0,0);
#pragma unroll
            for (int i = 0; i < 4; i++)
                rb[i] = *(const float4*)&B[(size_t)(k0 + bkr + i * 4) * N + n0 + bn4 * 4];
        }

#pragma unroll
        for (int kk = 0; kk < 2; kk++) {
            uint32_t af[4][4];
            uint32_t bf[8][2];
            const int kb = kk * 8;
#pragma unroll
            for (int fm = 0; fm < 4; fm++) {
                int mm = wm * 64 + fm * 16 + g;
                af[fm][0] = AS(buf, kb + c,     mm);
                af[fm][1] = AS(buf, kb + c,     mm + 8);
                af[fm][2] = AS(buf, kb + c + 4, mm);
                af[fm][3] = AS(buf, kb + c + 4, mm + 8);
            }
#pragma unroll
            for (int fn = 0; fn < 8; fn++) {
                int nn = wn * 64 + fn * 8 + g;
                bf[fn][0] = BS(buf, kb + c,     nn);
                bf[fn][1] = BS(buf, kb + c + 4, nn);
            }
#pragma unroll
            for (int fm = 0; fm < 4; fm++)
#pragma unroll
                for (int fn = 0; fn < 8; fn++) {
                    asm volatile(
                        "mma.sync.aligned.m16n8k8.row.col.f32.tf32.tf32.f32 "
                        "{%0,%1,%2,%3}, {%4,%5,%6,%7}, {%8,%9}, {%0,%1,%2,%3};"
                        : "+f"(acc[fm][fn][0]), "+f"(acc[fm][fn][1]),
                          "+f"(acc[fm][fn][2]), "+f"(acc[fm][fn][3])
                        : "r"(af[fm][0]), "r"(af[fm][1]), "r"(af[fm][2]), "r"(af[fm][3]),
                          "r"(bf[fn][0]), "r"(bf[fn][1]));
                }
        }

        if (tt + 1 < nt) {
            const int nbuf = 1 - buf;
            const float* rap = (const float*)ra;
#pragma unroll
            for (int j = 0; j < 8; j++) AS(nbuf, ak8 + j, arow) = f2tf(rap[j]);
#pragma unroll
            for (int i = 0; i < 4; i++) {
                int kr = bkr + i * 4;
                BS(nbuf, kr, bn4 * 4 + 0) = f2tf(rb[i].x);
                BS(nbuf, kr, bn4 * 4 + 1) = f2tf(rb[i].y);
                BS(nbuf, kr, bn4 * 4 + 2) = f2tf(rb[i].z);
                BS(nbuf, kr, bn4 * 4 + 3) = f2tf(rb[i].w);
            }
        }
    }

#pragma unroll
    for (int fm = 0; fm < 4; fm++) {
        int r0 = m0 + wm * 64 + fm * 16 + g;
        int r1 = r0 + 8;
#pragma unroll
        for (int fn = 0; fn < 8; fn++) {
            int col = n0 + wn * 64 + fn * 8 + c * 2;
            if (r0 < M)
                *(float2*)&H[(size_t)r0 * N + col] = make_float2(acc[fm][fn][0], acc[fm][fn][1]);
            if (r1 < M)
                *(float2*)&H[(size_t)r1 * N + col] = make_float2(acc[fm][fn][2], acc[fm][fn][3]);
        }
    }
}

// ---------------------------------------------------------------------------
// GEMM2: 128x128 block, warp 32x64, BK=16, static smem. H = A @ B (raw).
// ---------------------------------------------------------------------------
__global__ __launch_bounds__(256, 2)
void k_gemm_tf32(const float* __restrict__ A, const float* __restrict__ B,
                 float* __restrict__ H, int M, int N, int K)
{
    __shared__ uint32_t As[2][16][136];
    __shared__ uint32_t Bs[2][16][136];

    const int t    = threadIdx.x;
    const int lane = t & 31;
    const int wid  = t >> 5;
    const int wm   = wid >> 1;
    const int wn   = wid & 1;
    const int g    = lane >> 2;
    const int c    = lane & 3;
    const int m0   = blockIdx.y * 128;
    const int n0   = blockIdx.x * 128;

    const int arow = t >> 2;
    const int ac4  = t & 3;
    const int bkr  = t >> 5;
    const int bn4  = t & 31;

    float acc[2][8][4];
#pragma unroll
    for (int i = 0; i < 2; i++)
#pragma unroll
        for (int j = 0; j < 8; j++)
#pragma unroll
            for (int q = 0; q < 4; q++) acc[i][j][q] = 0.0f;

    const int nt = K / 16;
    float4 ra[2], rb[2];

#pragma unroll
    for (int it = 0; it < 2; it++) {
        int row = arow + it * 64;
        ra[it] = (m0 + row < M) ? *(const float4*)&A[(size_t)(m0 + row) * K + ac4 * 4]
                                : make_float4(0.f, 0.f, 0.f, 0.f);
        rb[it] = *(const float4*)&B[(size_t)(bkr + it * 8) * N + n0 + bn4 * 4];
    }
#pragma unroll
    for (int it = 0; it < 2; it++) {
        int row = arow + it * 64;
        As[0][ac4 * 4 + 0][row] = f2tf(ra[it].x);
        As[0][ac4 * 4 + 1][row] = f2tf(ra[it].y);
        As[0][ac4 * 4 + 2][row] = f2tf(ra[it].z);
        As[0][ac4 * 4 + 3][row] = f2tf(ra[it].w);
        int kr = bkr + it * 8;
        Bs[0][kr][bn4 * 4 + 0] = f2tf(rb[it].x);
        Bs[0][kr][bn4 * 4 + 1] = f2tf(rb[it].y);
        Bs[0][kr][bn4 * 4 + 2] = f2tf(rb[it].z);
        Bs[0][kr][bn4 * 4 + 3] = f2tf(rb[it].w);
    }

    for (int tt = 0; tt < nt; tt++) {
        __syncthreads();
        const int buf = tt & 1;

        if (tt + 1 < nt) {
            int k0 = (tt + 1) * 16;
#pragma unroll
            for (int it = 0; it < 2; it++) {
                int row = arow + it * 64;
                ra[it] = (m0 + row < M) ? *(const float4*)&A[(size_t)(m0 + row) * K + k0 + ac4 * 4]
                                        : make_float4(0.f, 0.f, 0.f, 0.f);
                rb[it] = *(const float4*)&B[(size_t)(k0 + bkr + it * 8) * N + n0 + bn4 * 4];
            }
        }

#pragma unroll
        for (int kk = 0; kk < 2; kk++) {
            uint32_t af[2][4];
            uint32_t bf[8][2];
            const int kb = kk * 8;
#pragma unroll
            for (int fm = 0; fm < 2; fm++) {
                int mm = wm * 32 + fm * 16 + g;
                af[fm][0] = As[buf][kb + c][mm];
                af[fm][1] = As[buf][kb + c][mm + 8];
                af[fm][2] = As[buf][kb + c + 4][mm];
                af[fm][3] = As[buf][kb + c + 4][mm + 8];
            }
#pragma unroll
            for (int fn = 0; fn < 8; fn++) {
                int nn = wn * 64 + fn * 8 + g;
                bf[fn][0] = Bs[buf][kb + c][nn];
                bf[fn][1] = Bs[buf][kb + c + 4][nn];
            }
#pragma unroll
            for (int fm = 0; fm < 2; fm++)
#pragma unroll
                for (int fn = 0; fn < 8; fn++) {
                    asm volatile(
                        "mma.sync.aligned.m16n8k8.row.col.f32.tf32.tf32.f32 "
                        "{%0,%1,%2,%3}, {%4,%5,%6,%7}, {%8,%9}, {%0,%1,%2,%3};"
                        : "+f"(acc[fm][fn][0]), "+f"(acc[fm][fn][1]),
                          "+f"(acc[fm][fn][2]), "+f"(acc[fm][fn][3])
                        : "r"(af[fm][0]), "r"(af[fm][1]), "r"(af[fm][2]), "r"(af[fm][3]),
                          "r"(bf[fn][0]), "r"(bf[fn][1]));
                }
        }

        if (tt + 1 < nt) {
            const int nbuf = 1 - buf;
#pragma unroll
            for (int it = 0; it < 2; it++) {
                int row = arow + it * 64;
                As[nbuf][ac4 * 4 + 0][row] = f2tf(ra[it].x);
                As[nbuf][ac4 * 4 + 1][row] = f2tf(ra[it].y);
                As[nbuf][ac4 * 4 + 2][row] = f2tf(ra[it].z);
                As[nbuf][ac4 * 4 + 3][row] = f2tf(ra[it].w);
                int kr = bkr + it * 8;
                Bs[nbuf][kr][bn4 * 4 + 0] = f2tf(rb[it].x);
                Bs[nbuf][kr][bn4 * 4 + 1] = f2tf(rb[it].y);
                Bs[nbuf][kr][bn4 * 4 + 2] = f2tf(rb[it].z);
                Bs[nbuf][kr][bn4 * 4 + 3] = f2tf(rb[it].w);
            }
        }
    }

#pragma unroll
    for (int fm = 0; fm < 2; fm++) {
        int r0 = m0 + wm * 32 + fm * 16 + g;
        int r1 = r0 + 8;
#pragma unroll
        for (int fn = 0; fn < 8; fn++) {
            int col = n0 + wn * 64 + fn * 8 + c * 2;
            if (r0 < M)
                *(float2*)&H[(size_t)r0 * N + col] = make_float2(acc[fm][fn][0], acc[fm][fn][1]);
            if (r1 < M)
                *(float2*)&H[(size_t)r1 * N + col] = make_float2(acc[fm][fn][2], acc[fm][fn][3]);
        }
    }
}

// ---------------------------------------------------------------------------
// pull aggregation (warp-per-dst-chunk, coalesced edge loads via shfl):
// out[i, chunk] = b + dinv[i]*( h[i,chunk]*dinv[i] + sum_e h[col[e],chunk]*dinv[col[e]] )
// One warp = one dst row x 32 float4 lanes (128 floats).
// ---------------------------------------------------------------------------
template <int F4TOT>
__global__ void k_pull_w(const int* __restrict__ rowp, const int* __restrict__ colA,
                         const float* __restrict__ hs, const float* __restrict__ dinv,
                         const float* __restrict__ bias, float* __restrict__ out,
                         int n, int fbase) {
    int warp = (blockIdx.x * blockDim.x + threadIdx.x) >> 5;
    int lane = threadIdx.x & 31;
    if (warp >= n) return;
    int dst = warp;
    int f4  = fbase + lane;

    const float4* h4 = (const float4*)hs;
    float dd = __ldg(&dinv[dst]);
    float4 acc = h4[(size_t)dst * F4TOT + f4];
    acc.x *= dd; acc.y *= dd; acc.z *= dd; acc.w *= dd;   // self: h[i]*dinv[i]

    int e0 = __ldg(&rowp[dst]);
    int e1 = __ldg(&rowp[dst + 1]);

    for (int eb = e0; eb < e1; eb += 32) {
        int idx = eb + lane;
        int cl = 0; float ds = 0.0f;
        if (idx < e1) {
            cl = __ldg(&colA[idx]);
            ds = __ldg(&dinv[cl]);
        }
        int m = min(32, e1 - eb);
#pragma unroll 4
        for (int j = 0; j < m; j++) {
            int   s = __shfl_sync(0xFFFFFFFFu, cl, j);
            float w = __shfl_sync(0xFFFFFFFFu, ds, j);
            float4 v = h4[(size_t)s * F4TOT + f4];
            acc.x += v.x * w; acc.y += v.y * w; acc.z += v.z * w; acc.w += v.w * w;
        }
    }

    float4 bb = ((const float4*)bias)[f4];
    float4 o = make_float4(bb.x + acc.x * dd, bb.y + acc.y * dd,
                           bb.z + acc.z * dd, bb.w + acc.w * dd);
    __stcs(&((float4*)out)[(size_t)dst * F4TOT + f4], o);
}

// ---------------------------------------------------------------------------
extern "C" void kernel_launch(void* const* d_in, const int* in_sizes, int n_in,
                              void* d_out, int out_size) {
    const float* x   = (const float*)d_in[0];
    const void*  ei  = d_in[1];
    const float* W1  = (const float*)d_in[3];
    const float* b1  = (const float*)d_in[4];
    const float* W2  = (const float*)d_in[5];
    const float* b2  = (const float*)d_in[6];
    float*       out = (float*)d_out;

    const long long nelem = (long long)in_sizes[1];
    const long long E     = nelem / 2;
    const int dhid        = in_sizes[4];         // 512
    const int dout        = in_sizes[6];         // 128
    const int din         = in_sizes[3] / dhid;  // 512
    const int n           = in_sizes[0] / din;   // 100000

    float *dinv_p, *h_p, *agg_p;
    int *cnt_p, *rowp_p, *cur_p, *col_p, *bsum_p;
    cudaGetSymbolAddress((void**)&dinv_p, g_dinv);
    cudaGetSymbolAddress((void**)&h_p,    g_h);
    cudaGetSymbolAddress((void**)&agg_p,  g_agg);
    cudaGetSymbolAddress((void**)&cnt_p,  g_cnt);
    cudaGetSymbolAddress((void**)&rowp_p, g_rowp);
    cudaGetSymbolAddress((void**)&cur_p,  g_cur);
    cudaGetSymbolAddress((void**)&col_p,  g_col);
    cudaGetSymbolAddress((void**)&bsum_p, g_bsum);

    static bool attr_set = false;
    if (!attr_set) {
        cudaFuncSetAttribute(k_gemm256, cudaFuncAttributeMaxDynamicSharedMemorySize, G1_SMEM);
        attr_set = true;
    }

    const int eb = (int)((E + 255) / 256);
    const int nb = (n + 255) / 256;
    const int nblk = (n + 1023) / 1024;
    const int pull_blocks = (int)(((long long)n * 32 + 255) / 256);

    // Launch order: GEMM1 is the 4th launch (ncu capture slot).
    k_detect<<<1, 32>>>(ei, nelem, n);                                 // 1
    k_zero_cnt<<<nb, 256>>>(cnt_p, n);                                 // 2
    k_hist<<<eb, 256>>>(ei, E, cnt_p);                                 // 3
    {
        dim3 grid(dhid / 256, (n + 127) / 128);
        k_gemm256<<<grid, 256, G1_SMEM>>>(x, W1, h_p, n, dhid, din);   // 4 <-- profiled
    }
    k_scan_blk<<<nblk, 1024>>>(cnt_p, rowp_p, bsum_p, n);              // 5
    k_scan_top<<<1, 1024>>>(bsum_p, nblk);                             // 6
    k_scan_add<<<(n + 256) / 256, 256>>>(rowp_p, bsum_p, n, nblk);     // 7
    k_dinv_cursor<<<nb, 256>>>(cnt_p, rowp_p, dinv_p, cur_p, n);       // 8
    k_scatter<<<eb, 256>>>(ei, E, cur_p, col_p);                       // 9

    // layer-1 pull: 4 feature-chunk passes (L2-resident 51 MB gather set each)
    for (int cidx = 0; cidx < 4; cidx++) {
        k_pull_w<128><<<pull_blocks, 256>>>(rowp_p, col_p, h_p, dinv_p,
                                            b1, agg_p, n, cidx * 32);
    }

    // layer 2
    {
        dim3 grid(dout / 128, (n + 127) / 128);
        k_gemm_tf32<<<grid, 256>>>(agg_p, W2, h_p, n, dout, dhid);
        k_pull_w<32><<<pull_blocks, 256>>>(rowp_p, col_p, h_p, dinv_p,
                                           b2, out, n, 0);
    }

    (void)n_in; (void)out_size;
}

// round 7
// speedup vs baseline: 1.0374x; 1.0374x over previous
#include <cuda_runtime.h>
#include <cuda_bf16.h>
#include <stdint.h>

// ---------------------------------------------------------------------------
// GCN 2-layer. GEMMs = mma.sync tf32 with ldmatrix fragment loads (sm_103-safe).
//   dinv = (1+indeg)^-0.5 ;  hs = (x@W) * dinv[row]   (GEMM epilogue)
//   out[i] = b + dinv[i] * ( hs[i] + sum_{e:dst=i} hs[src] )   (CSR pull)
// ---------------------------------------------------------------------------

#define MAXN 100352
#define MAXE 1048576
#define MAXF 512

__device__ float g_dinv[MAXN];
__device__ float g_h[(size_t)MAXN * MAXF];
__device__ float g_agg[(size_t)MAXN * MAXF];
__device__ float g_wt1[(size_t)512 * 512];   // W1^T, tf32-rounded, [n][k]
__device__ float g_wt2[(size_t)128 * 512];   // W2^T, tf32-rounded, [n][k]
__device__ int   g_cnt[MAXN];
__device__ int   g_rowp[MAXN + 1];
__device__ int   g_cur[MAXN];
__device__ int   g_col[MAXE];
__device__ int   g_bsum[1025];
__device__ int   g_is64;

// ------------------------------- helpers -----------------------------------
__device__ __forceinline__ uint32_t smem_u32(const void* p) {
    uint32_t a;
    asm("{ .reg .u64 t; cvta.to.shared.u64 t, %1; cvt.u32.u64 %0, t; }" : "=r"(a) : "l"(p));
    return a;
}
__device__ __forceinline__ uint32_t f2tf(float x) {
    uint32_t u;
    asm("cvt.rna.tf32.f32 %0, %1;" : "=r"(u) : "f"(x));
    return u;
}
__device__ __forceinline__ void ldsm_x4(uint32_t& r0, uint32_t& r1, uint32_t& r2, uint32_t& r3,
                                        uint32_t addr) {
    asm volatile("ldmatrix.sync.aligned.m8n8.x4.shared.b16 {%0,%1,%2,%3}, [%4];"
                 : "=r"(r0), "=r"(r1), "=r"(r2), "=r"(r3) : "r"(addr));
}
__device__ __forceinline__ void cp_async16(uint32_t dst, const void* src) {
    asm volatile("cp.async.ca.shared.global [%0], [%1], 16;" :: "r"(dst), "l"(src) : "memory");
}
#define CP_COMMIT() asm volatile("cp.async.commit_group;" ::: "memory")
#define CP_WAIT0()  asm volatile("cp.async.wait_group 0;" ::: "memory")

__device__ __forceinline__ long long edge_at(const void* ei, long long idx, int is64) {
    if (is64) return ((const long long*)ei)[idx];
    return (long long)((const int*)ei)[idx];
}

// ---------------------------------------------------------------------------
// setup kernels
// ---------------------------------------------------------------------------
__global__ void k_init(const void* ei, long long nelem, int n, int* cnt) {
    int i = blockIdx.x * blockDim.x + threadIdx.x;
    if (i < n) cnt[i] = 0;
    if (blockIdx.x == 0 && threadIdx.x == 0) {
        const long long* p = (const long long*)ei;
        long long m = 64;
        if (m > nelem / 2) m = nelem / 2;
        int is64 = 1;
        for (long long j = 0; j < m; j++) {
            long long v = p[j];
            if (v < 0 || v >= (long long)n) { is64 = 0; break; }
        }
        g_is64 = is64;
    }
}

// W [K,N] -> Wt [N,K], tf32-rounded.
__global__ void k_transpose(const float* __restrict__ W, float* __restrict__ Wt, int K, int N) {
    __shared__ float tile[32][33];
    int k0 = blockIdx.y * 32, n0 = blockIdx.x * 32;
    int tx = threadIdx.x, ty = threadIdx.y;  // 32 x 8
    for (int j = 0; j < 32; j += 8)
        tile[ty + j][tx] = W[(size_t)(k0 + ty + j) * N + n0 + tx];
    __syncthreads();
    for (int j = 0; j < 32; j += 8) {
        uint32_t u = f2tf(tile[tx][ty + j]);
        Wt[(size_t)(n0 + ty + j) * K + k0 + tx] = __uint_as_float(u);
    }
}

__global__ void k_hist(const void* __restrict__ ei, long long E, int* __restrict__ cnt) {
    long long i = (long long)blockIdx.x * blockDim.x + threadIdx.x;
    if (i >= E) return;
    int d = (int)edge_at(ei, E + i, g_is64);
    atomicAdd(&cnt[d], 1);
}

__global__ void k_scan_blk(const int* __restrict__ cnt, int* __restrict__ rowp,
                           int* __restrict__ bsum, int n) {
    __shared__ int warpsum[32];
    const int t = threadIdx.x, lane = t & 31, w = t >> 5;
    int i = blockIdx.x * 1024 + t;
    int v = (i < n) ? cnt[i] : 0;
    int x = v;
#pragma unroll
    for (int off = 1; off < 32; off <<= 1) {
        int y = __shfl_up_sync(0xFFFFFFFFu, x, off);
        if (lane >= off) x += y;
    }
    if (lane == 31) warpsum[w] = x;
    __syncthreads();
    if (w == 0) {
        int s = warpsum[lane];
#pragma unroll
        for (int off = 1; off < 32; off <<= 1) {
            int y = __shfl_up_sync(0xFFFFFFFFu, s, off);
            if (lane >= off) s += y;
        }
        warpsum[lane] = s;
    }
    __syncthreads();
    int wpre = (w > 0) ? warpsum[w - 1] : 0;
    if (i < n) rowp[i] = x - v + wpre;
    if (t == 1023) bsum[blockIdx.x] = wpre + x;
}

__global__ void k_scan_top(int* __restrict__ bsum, int nb) {
    __shared__ int warpsum[32];
    const int t = threadIdx.x, lane = t & 31, w = t >> 5;
    int v = (t < nb) ? bsum[t] : 0;
    int x = v;
#pragma unroll
    for (int off = 1; off < 32; off <<= 1) {
        int y = __shfl_up_sync(0xFFFFFFFFu, x, off);
        if (lane >= off) x += y;
    }
    if (lane == 31) warpsum[w] = x;
    __syncthreads();
    if (w == 0) {
        int s = warpsum[lane];
#pragma unroll
        for (int off = 1; off < 32; off <<= 1) {
            int y = __shfl_up_sync(0xFFFFFFFFu, s, off);
            if (lane >= off) s += y;
        }
        warpsum[lane] = s;
    }
    __syncthreads();
    int wpre = (w > 0) ? warpsum[w - 1] : 0;
    if (t < nb) bsum[t] = x - v + wpre;
    if (t == 1023) bsum[nb] = warpsum[31];
}

__global__ void k_scan_add(int* __restrict__ rowp, const int* __restrict__ bsum, int n, int nb) {
    int i = blockIdx.x * blockDim.x + threadIdx.x;
    if (i < n) rowp[i] += bsum[i >> 10];
    if (i == n) rowp[n] = bsum[nb];
}

__global__ void k_dinv_cursor(const int* __restrict__ cnt, const int* __restrict__ rowp,
                              float* __restrict__ dinv, int* __restrict__ cur, int n) {
    int i = blockIdx.x * blockDim.x + threadIdx.x;
    if (i >= n) return;
    dinv[i] = rsqrtf((float)cnt[i] + 1.0f);
    cur[i]  = rowp[i];
}

__global__ void k_scatter(const void* __restrict__ ei, long long E,
                          int* __restrict__ cur, int* __restrict__ colA) {
    long long i = (long long)blockIdx.x * blockDim.x + threadIdx.x;
    if (i >= E) return;
    int is64 = g_is64;
    int s = (int)edge_at(ei, i, is64);
    int d = (int)edge_at(ei, E + i, is64);
    int pos = atomicAdd(&cur[d], 1);
    colA[pos] = s;
}

// ---------------------------------------------------------------------------
// GEMM (ldmatrix + mma.sync tf32): Hs[M,N] = (A[M,K] @ Wt[N,K]^T) * dinv(row)
// 128x128 block, BK=16, 256 threads (8 warps 4x2), warp tile 32x64.
// smem quad-major: slot = kq*128 + row (16B slots); A manual-staged (cvt.rna),
// B via cp.async (Wt pre-rounded). dinv(r) = rsqrt(cnt[r]+1).
// Requires N % 128 == 0, K % 16 == 0. M guarded.
// ---------------------------------------------------------------------------
__global__ __launch_bounds__(256, 2)
void k_gemm_ldsm(const float* __restrict__ A, const float* __restrict__ Bt,
                 const int* __restrict__ cnt, float* __restrict__ Hs,
                 int M, int N, int K)
{
    __shared__ __align__(16) char smem[32768];  // A: [2][8KB] @0, B: [2][8KB] @16384
    const uint32_t sbA = smem_u32(smem);
    const uint32_t sbB = sbA + 16384;

    const int t    = threadIdx.x;
    const int L    = t & 31;
    const int wid  = t >> 5;
    const int wm   = wid >> 1;        // 0..3
    const int wn   = wid & 1;         // 0..1
    const int g    = L >> 2;
    const int c    = L & 3;
    const int m0   = blockIdx.y * 128;
    const int n0   = blockIdx.x * 128;

    // ldmatrix per-lane base offsets (bytes)
    const uint32_t aLane = ((uint32_t)(L >> 4)) * 2048u
                         + (((uint32_t)(L & 7)) + ((uint32_t)((L >> 3) & 1)) * 8u) * 16u
                         + (uint32_t)wm * 512u;
    const uint32_t bLane = ((uint32_t)((L >> 3) & 1)) * 2048u
                         + (((uint32_t)(L >> 4)) * 8u + ((uint32_t)(L & 7))) * 16u
                         + (uint32_t)wn * 1024u;

    // staging constants
    const int srow = t >> 1;           // 0..127 (A row / B n-row)
    const int shalf = t & 1;           // k-half: quads 2*shalf, 2*shalf+1
    const uint32_t sAoff = ((uint32_t)(2 * shalf)) * 2048u + (uint32_t)srow * 16u;

    float acc[2][8][4];
#pragma unroll
    for (int i = 0; i < 2; i++)
#pragma unroll
        for (int j = 0; j < 8; j++)
#pragma unroll
            for (int q = 0; q < 4; q++) acc[i][j][q] = 0.0f;

    const int nkt = K >> 4;
    const bool mval = (m0 + srow) < M;

    // ---- prologue: stage ktile 0 into buf 0 ----
    {
        const float* ga = A + (size_t)(m0 + srow) * K + shalf * 8;
        float4 ra0 = mval ? *(const float4*)ga       : make_float4(0, 0, 0, 0);
        float4 ra1 = mval ? *(const float4*)(ga + 4) : make_float4(0, 0, 0, 0);
        *(uint4*)(smem + sAoff)        = make_uint4(f2tf(ra0.x), f2tf(ra0.y), f2tf(ra0.z), f2tf(ra0.w));
        *(uint4*)(smem + sAoff + 2048) = make_uint4(f2tf(ra1.x), f2tf(ra1.y), f2tf(ra1.z), f2tf(ra1.w));
        const float* gb = Bt + (size_t)(n0 + srow) * K + shalf * 8;
        cp_async16(sbB + sAoff, gb);
        cp_async16(sbB + sAoff + 2048, gb + 4);
        CP_COMMIT();
        CP_WAIT0();
    }
    __syncthreads();

    for (int kt = 0; kt < nkt; kt++) {
        const int buf = kt & 1;
        const int nbuf = 1 - buf;
        const bool nxt = (kt + 1) < nkt;

        float4 ra0, ra1;
        if (nxt) {
            const int k0 = (kt + 1) * 16;
            const float* ga = A + (size_t)(m0 + srow) * K + k0 + shalf * 8;
            ra0 = mval ? *(const float4*)ga       : make_float4(0, 0, 0, 0);
            ra1 = mval ? *(const float4*)(ga + 4) : make_float4(0, 0, 0, 0);
            const float* gb = Bt + (size_t)(n0 + srow) * K + k0 + shalf * 8;
            uint32_t bdst = sbB + nbuf * 8192u + sAoff;
            cp_async16(bdst, gb);
            cp_async16(bdst + 2048, gb + 4);
            CP_COMMIT();
        }

        // ---- compute on buf: 2 k-octets ----
        const uint32_t aB = sbA + buf * 8192u + aLane;
        const uint32_t bB = sbB + buf * 8192u + bLane;
#pragma unroll
        for (int kk = 0; kk < 2; kk++) {
            uint32_t af[2][4];
            uint32_t bf[8][2];
#pragma unroll
            for (int fm = 0; fm < 2; fm++)
                ldsm_x4(af[fm][0], af[fm][1], af[fm][2], af[fm][3],
                        aB + kk * 4096u + fm * 256u);
#pragma unroll
            for (int p = 0; p < 4; p++)
                ldsm_x4(bf[2 * p][0], bf[2 * p][1], bf[2 * p + 1][0], bf[2 * p + 1][1],
                        bB + kk * 4096u + p * 256u);
#pragma unroll
            for (int fm = 0; fm < 2; fm++)
#pragma unroll
                for (int fn = 0; fn < 8; fn++) {
                    asm volatile(
                        "mma.sync.aligned.m16n8k8.row.col.f32.tf32.tf32.f32 "
                        "{%0,%1,%2,%3}, {%4,%5,%6,%7}, {%8,%9}, {%0,%1,%2,%3};"
                        : "+f"(acc[fm][fn][0]), "+f"(acc[fm][fn][1]),
                          "+f"(acc[fm][fn][2]), "+f"(acc[fm][fn][3])
                        : "r"(af[fm][0]), "r"(af[fm][1]), "r"(af[fm][2]), "r"(af[fm][3]),
                          "r"(bf[fn][0]), "r"(bf[fn][1]));
                }
        }

        if (nxt) {
            char* ad = smem + nbuf * 8192u + sAoff;
            *(uint4*)ad          = make_uint4(f2tf(ra0.x), f2tf(ra0.y), f2tf(ra0.z), f2tf(ra0.w));
            *(uint4*)(ad + 2048) = make_uint4(f2tf(ra1.x), f2tf(ra1.y), f2tf(ra1.z), f2tf(ra1.w));
            CP_WAIT0();
        }
        __syncthreads();
    }

    // ---- epilogue: scale by dinv(row) = rsqrt(cnt+1), store ----
#pragma unroll
    for (int fm = 0; fm < 2; fm++) {
        int r0 = m0 + wm * 32 + fm * 16 + g;
        int r1 = r0 + 8;
        float d0 = (r0 < M) ? rsqrtf((float)__ldg(&cnt[r0]) + 1.0f) : 0.0f;
        float d1 = (r1 < M) ? rsqrtf((float)__ldg(&cnt[r1]) + 1.0f) : 0.0f;
#pragma unroll
        for (int fn = 0; fn < 8; fn++) {
            int col = n0 + wn * 64 + fn * 8 + c * 2;
            if (r0 < M)
                *(float2*)&Hs[(size_t)r0 * N + col] = make_float2(acc[fm][fn][0] * d0, acc[fm][fn][1] * d0);
            if (r1 < M)
                *(float2*)&Hs[(size_t)r1 * N + col] = make_float2(acc[fm][fn][2] * d1, acc[fm][fn][3] * d1);
        }
    }
}

// ---------------------------------------------------------------------------
// pull aggregation (R4 chunked): thread = (dst, f4-in-chunk); hs pre-scaled.
// ---------------------------------------------------------------------------
template <int F4TOT, int F4C>
__global__ void k_pull_c(const int* __restrict__ rowp, const int* __restrict__ colA,
                         const float* __restrict__ hs, const float* __restrict__ dinv,
                         const float* __restrict__ bias, float* __restrict__ out,
                         int n, int fbase) {
    int idx = blockIdx.x * blockDim.x + threadIdx.x;
    int dst = idx / F4C;
    int j   = idx % F4C;
    if (dst >= n) return;
    int f4 = fbase + j;
    const float4* h4 = (const float4*)hs;
    float4 acc = h4[(size_t)dst * F4TOT + f4];   // self loop (hs already *dinv[src])
    int e0 = __ldg(&rowp[dst]);
    int e1 = __ldg(&rowp[dst + 1]);
    for (int e = e0; e < e1; e++) {
        int s = __ldg(&colA[e]);
        float4 v = h4[(size_t)s * F4TOT + f4];
        acc.x += v.x; acc.y += v.y; acc.z += v.z; acc.w += v.w;
    }
    float d = dinv[dst];
    float4 bb = ((const float4*)bias)[f4];
    float4 o = make_float4(bb.x + acc.x * d, bb.y + acc.y * d,
                           bb.z + acc.z * d, bb.w + acc.w * d);
    __stcs(&((float4*)out)[(size_t)dst * F4TOT + f4], o);
}

// ---------------------------------------------------------------------------
extern "C" void kernel_launch(void* const* d_in, const int* in_sizes, int n_in,
                              void* d_out, int out_size) {
    const float* x   = (const float*)d_in[0];
    const void*  ei  = d_in[1];
    const float* W1  = (const float*)d_in[3];
    const float* b1  = (const float*)d_in[4];
    const float* W2  = (const float*)d_in[5];
    const float* b2  = (const float*)d_in[6];
    float*       out = (float*)d_out;

    const long long nelem = (long long)in_sizes[1];
    const long long E     = nelem / 2;
    const int dhid        = in_sizes[4];         // 512
    const int dout        = in_sizes[6];         // 128
    const int din         = in_sizes[3] / dhid;  // 512
    const int n           = in_sizes[0] / din;   // 100000

    float *dinv_p, *h_p, *agg_p, *wt1_p, *wt2_p;
    int *cnt_p, *rowp_p, *cur_p, *col_p, *bsum_p;
    cudaGetSymbolAddress((void**)&dinv_p, g_dinv);
    cudaGetSymbolAddress((void**)&h_p,    g_h);
    cudaGetSymbolAddress((void**)&agg_p,  g_agg);
    cudaGetSymbolAddress((void**)&wt1_p,  g_wt1);
    cudaGetSymbolAddress((void**)&wt2_p,  g_wt2);
    cudaGetSymbolAddress((void**)&cnt_p,  g_cnt);
    cudaGetSymbolAddress((void**)&rowp_p, g_rowp);
    cudaGetSymbolAddress((void**)&cur_p,  g_cur);
    cudaGetSymbolAddress((void**)&col_p,  g_col);
    cudaGetSymbolAddress((void**)&bsum_p, g_bsum);

    const int eb   = (int)((E + 255) / 256);
    const int nb   = (n + 255) / 256;
    const int nblk = (n + 1023) / 1024;

    // 1: zero cnt + dtype detect
    k_init<<<nb, 256>>>(ei, nelem, n, cnt_p);
    // 2: W1^T (tf32-rounded)
    {
        dim3 grid(dhid / 32, din / 32), blk(32, 8);
        k_transpose<<<grid, blk>>>(W1, wt1_p, din, dhid);
    }
    // 3: degree histogram
    k_hist<<<eb, 256>>>(ei, E, cnt_p);
    // 4: GEMM1 (ldmatrix tf32) -- profiled slot
    {
        dim3 grid(dhid / 128, (n + 127) / 128);
        k_gemm_ldsm<<<grid, 256>>>(x, wt1_p, cnt_p, h_p, n, dhid, din);
    }
    // 5: W2^T
    {
        dim3 grid(dout / 32, dhid / 32), blk(32, 8);
        k_transpose<<<grid, blk>>>(W2, wt2_p, dhid, dout);
    }
    // 6-10: CSR build
    k_scan_blk<<<nblk, 1024>>>(cnt_p, rowp_p, bsum_p, n);
    k_scan_top<<<1, 1024>>>(bsum_p, nblk);
    k_scan_add<<<(n + 256) / 256, 256>>>(rowp_p, bsum_p, n, nblk);
    k_dinv_cursor<<<nb, 256>>>(cnt_p, rowp_p, dinv_p, cur_p, n);
    k_scatter<<<eb, 256>>>(ei, E, cur_p, col_p);

    // layer-1 pull: 4 feature-chunk passes (51 MB gather footprint each)
    int tot = n * 32;
    for (int cidx = 0; cidx < 4; cidx++) {
        k_pull_c<128, 32><<<(tot + 255) / 256, 256>>>(rowp_p, col_p, h_p, dinv_p,
                                                      b1, agg_p, n, cidx * 32);
    }

    // layer 2
    {
        dim3 grid(dout / 128, (n + 127) / 128);
        k_gemm_ldsm<<<grid, 256>>>(agg_p, wt2_p, cnt_p, h_p, n, dout, dhid);
        k_pull_c<32, 32><<<(tot + 255) / 256, 256>>>(rowp_p, col_p, h_p, dinv_p,
                                                     b2, out, n, 0);
    }

    (void)n_in; (void)out_size;
}

// round 8
// speedup vs baseline: 1.1228x; 1.0824x over previous
#include <cuda_runtime.h>
#include <cuda_fp16.h>
#include <stdint.h>

// ---------------------------------------------------------------------------
// GCN 2-layer. GEMMs = mma.sync fp16 m16n8k16 (fp32 accum) + ldmatrix.
//   dinv = (1+indeg)^-0.5 ;  hs = (x@W) * dinv[row]   (GEMM epilogue)
//   out[i] = b + dinv[i] * ( hs[i] + sum_{e:dst=i} hs[src] )   (CSR pull)
// ---------------------------------------------------------------------------

#define MAXN 100352
#define MAXE 1048576
#define MAXF 512

__device__ float  g_dinv[MAXN];
__device__ float  g_h[(size_t)MAXN * MAXF];
__device__ float  g_agg[(size_t)MAXN * MAXF];
__device__ __half g_wt1[(size_t)512 * 512];   // W1^T fp16, [n][k]
__device__ __half g_wt2[(size_t)128 * 512];   // W2^T fp16, [n][k]
__device__ int    g_cnt[MAXN];
__device__ int    g_rowp[MAXN + 1];
__device__ int    g_cur[MAXN];
__device__ int    g_col[MAXE];
__device__ int    g_bsum[1025];
__device__ int    g_is64;

// ------------------------------- helpers -----------------------------------
__device__ __forceinline__ uint32_t smem_u32(const void* p) {
    uint32_t a;
    asm("{ .reg .u64 t; cvta.to.shared.u64 t, %1; cvt.u32.u64 %0, t; }" : "=r"(a) : "l"(p));
    return a;
}
__device__ __forceinline__ void ldsm_x4(uint32_t& r0, uint32_t& r1, uint32_t& r2, uint32_t& r3,
                                        uint32_t addr) {
    asm volatile("ldmatrix.sync.aligned.m8n8.x4.shared.b16 {%0,%1,%2,%3}, [%4];"
                 : "=r"(r0), "=r"(r1), "=r"(r2), "=r"(r3) : "r"(addr));
}
__device__ __forceinline__ void cp_async16(uint32_t dst, const void* src) {
    asm volatile("cp.async.ca.shared.global [%0], [%1], 16;" :: "r"(dst), "l"(src) : "memory");
}
#define CP_COMMIT() asm volatile("cp.async.commit_group;" ::: "memory")
#define CP_WAIT0()  asm volatile("cp.async.wait_group 0;" ::: "memory")

__device__ __forceinline__ uint32_t h2u(__half2 h) { return *(uint32_t*)&h; }

__device__ __forceinline__ long long edge_at(const void* ei, long long idx, int is64) {
    if (is64) return ((const long long*)ei)[idx];
    return (long long)((const int*)ei)[idx];
}

// ---------------------------------------------------------------------------
// setup kernels
// ---------------------------------------------------------------------------
__global__ void k_init(const void* ei, long long nelem, int n, int* cnt) {
    int i = blockIdx.x * blockDim.x + threadIdx.x;
    if (i < n) cnt[i] = 0;
    if (blockIdx.x == 0 && threadIdx.x == 0) {
        const long long* p = (const long long*)ei;
        long long m = 64;
        if (m > nelem / 2) m = nelem / 2;
        int is64 = 1;
        for (long long j = 0; j < m; j++) {
            long long v = p[j];
            if (v < 0 || v >= (long long)n) { is64 = 0; break; }
        }
        g_is64 = is64;
    }
}

// W [K,N] fp32 -> Wt [N,K] fp16.
__global__ void k_transpose_h(const float* __restrict__ W, __half* __restrict__ Wt, int K, int N) {
    __shared__ float tile[32][33];
    int k0 = blockIdx.y * 32, n0 = blockIdx.x * 32;
    int tx = threadIdx.x, ty = threadIdx.y;  // 32 x 8
    for (int j = 0; j < 32; j += 8)
        tile[ty + j][tx] = W[(size_t)(k0 + ty + j) * N + n0 + tx];
    __syncthreads();
    for (int j = 0; j < 32; j += 8)
        Wt[(size_t)(n0 + ty + j) * K + k0 + tx] = __float2half_rn(tile[tx][ty + j]);
}

__global__ void k_hist(const void* __restrict__ ei, long long E, int* __restrict__ cnt) {
    long long i = (long long)blockIdx.x * blockDim.x + threadIdx.x;
    if (i >= E) return;
    int d = (int)edge_at(ei, E + i, g_is64);
    atomicAdd(&cnt[d], 1);
}

__global__ void k_scan_blk(const int* __restrict__ cnt, int* __restrict__ rowp,
                           int* __restrict__ bsum, int n) {
    __shared__ int warpsum[32];
    const int t = threadIdx.x, lane = t & 31, w = t >> 5;
    int i = blockIdx.x * 1024 + t;
    int v = (i < n) ? cnt[i] : 0;
    int x = v;
#pragma unroll
    for (int off = 1; off < 32; off <<= 1) {
        int y = __shfl_up_sync(0xFFFFFFFFu, x, off);
        if (lane >= off) x += y;
    }
    if (lane == 31) warpsum[w] = x;
    __syncthreads();
    if (w == 0) {
        int s = warpsum[lane];
#pragma unroll
        for (int off = 1; off < 32; off <<= 1) {
            int y = __shfl_up_sync(0xFFFFFFFFu, s, off);
            if (lane >= off) s += y;
        }
        warpsum[lane] = s;
    }
    __syncthreads();
    int wpre = (w > 0) ? warpsum[w - 1] : 0;
    if (i < n) rowp[i] = x - v + wpre;
    if (t == 1023) bsum[blockIdx.x] = wpre + x;
}

__global__ void k_scan_top(int* __restrict__ bsum, int nb) {
    __shared__ int warpsum[32];
    const int t = threadIdx.x, lane = t & 31, w = t >> 5;
    int v = (t < nb) ? bsum[t] : 0;
    int x = v;
#pragma unroll
    for (int off = 1; off < 32; off <<= 1) {
        int y = __shfl_up_sync(0xFFFFFFFFu, x, off);
        if (lane >= off) x += y;
    }
    if (lane == 31) warpsum[w] = x;
    __syncthreads();
    if (w == 0) {
        int s = warpsum[lane];
#pragma unroll
        for (int off = 1; off < 32; off <<= 1) {
            int y = __shfl_up_sync(0xFFFFFFFFu, s, off);
            if (lane >= off) s += y;
        }
        warpsum[lane] = s;
    }
    __syncthreads();
    int wpre = (w > 0) ? warpsum[w - 1] : 0;
    if (t < nb) bsum[t] = x - v + wpre;
    if (t == 1023) bsum[nb] = warpsum[31];
}

__global__ void k_scan_add(int* __restrict__ rowp, const int* __restrict__ bsum, int n, int nb) {
    int i = blockIdx.x * blockDim.x + threadIdx.x;
    if (i < n) rowp[i] += bsum[i >> 10];
    if (i == n) rowp[n] = bsum[nb];
}

__global__ void k_dinv_cursor(const int* __restrict__ cnt, const int* __restrict__ rowp,
                              float* __restrict__ dinv, int* __restrict__ cur, int n) {
    int i = blockIdx.x * blockDim.x + threadIdx.x;
    if (i >= n) return;
    dinv[i] = rsqrtf((float)cnt[i] + 1.0f);
    cur[i]  = rowp[i];
}

__global__ void k_scatter(const void* __restrict__ ei, long long E,
                          int* __restrict__ cur, int* __restrict__ colA) {
    long long i = (long long)blockIdx.x * blockDim.x + threadIdx.x;
    if (i >= E) return;
    int is64 = g_is64;
    int s = (int)edge_at(ei, i, is64);
    int d = (int)edge_at(ei, E + i, is64);
    int pos = atomicAdd(&cur[d], 1);
    colA[pos] = s;
}

// ---------------------------------------------------------------------------
// GEMM fp16 (ldmatrix + mma.sync m16n8k16): Hs = (A @ Wt^T) * dinv(row)
// 128x128 block, BK=32, 256 threads (8 warps 4x2), warp tile 32x64.
// smem: 16B slots, slot = k8*128 + row. A staged via LDG+cvt (fp32 input),
// B via cp.async (Wt already fp16). dinv(r) = rsqrt(cnt[r]+1).
// Requires N % 128 == 0, K % 32 == 0. M guarded.
// ---------------------------------------------------------------------------
__global__ __launch_bounds__(256, 2)
void k_gemm_h(const float* __restrict__ A, const __half* __restrict__ Bt,
              const int* __restrict__ cnt, float* __restrict__ Hs,
              int M, int N, int K)
{
    __shared__ __align__(16) char smem[32768];  // A: [2][8KB] @0, B: [2][8KB] @16384
    const uint32_t sbA = smem_u32(smem);
    const uint32_t sbB = sbA + 16384;

    const int t   = threadIdx.x;
    const int L   = t & 31;
    const int wid = t >> 5;
    const int wm  = wid >> 1;        // 0..3 -> 32 rows
    const int wn  = wid & 1;         // 0..1 -> 64 cols
    const int g   = L >> 2;
    const int c   = L & 3;
    const int m0  = blockIdx.y * 128;
    const int n0  = blockIdx.x * 128;

    // ldmatrix lane-address components (slot units, 16B each)
    // A (q = L>>3): q&1 -> +8 rows handled via ((L>>3)&1)*8 ... mapping:
    //   a-regs: q0 rows0-7 k8lo, q1 rows8-15 k8lo, q2 rows0-7 k8hi, q3 rows8-15 k8hi
    const uint32_t aLane = ((uint32_t)((L >> 4) & 1)) * 128u   // k8 high
                         + (uint32_t)(wm * 32) + (uint32_t)(L & 7) + ((uint32_t)((L >> 3) & 1)) * 8u;
    //   b-regs: q0 rows(16p)+0-7 k8lo, q1 same rows k8hi, q2 rows+8 k8lo, q3 rows+8 k8hi
    const uint32_t bLane = ((uint32_t)((L >> 3) & 1)) * 128u   // k8 high
                         + (uint32_t)(wn * 64) + (uint32_t)(L & 7) + ((uint32_t)((L >> 4) & 1)) * 8u;

    // staging: 2 slots per thread per ktile; slot = t + 256*i
    const int s0 = t, s1 = t + 256;
    const int r0s = s0 & 127, k80 = s0 >> 7;   // k80 in {0,1}
    const int r1s = s1 & 127, k81 = s1 >> 7;   // k81 in {2,3}
    const bool mv0 = (m0 + r0s) < M;
    const bool mv1 = (m0 + r1s) < M;
    const uint32_t st0 = (uint32_t)(k80 * 128 + r0s) * 16u;
    const uint32_t st1 = (uint32_t)(k81 * 128 + r1s) * 16u;

    float acc[2][8][4];
#pragma unroll
    for (int i = 0; i < 2; i++)
#pragma unroll
        for (int j = 0; j < 8; j++)
#pragma unroll
            for (int q = 0; q < 4; q++) acc[i][j][q] = 0.0f;

    const int nkt = K >> 5;   // BK=32

    // ---- prologue: stage ktile 0 into buf 0 ----
    {
        const float* ga0 = A + (size_t)(m0 + r0s) * K + k80 * 8;
        const float* ga1 = A + (size_t)(m0 + r1s) * K + k81 * 8;
        float4 a00 = mv0 ? *(const float4*)ga0       : make_float4(0, 0, 0, 0);
        float4 a01 = mv0 ? *(const float4*)(ga0 + 4) : make_float4(0, 0, 0, 0);
        float4 a10 = mv1 ? *(const float4*)ga1       : make_float4(0, 0, 0, 0);
        float4 a11 = mv1 ? *(const float4*)(ga1 + 4) : make_float4(0, 0, 0, 0);
        *(uint4*)(smem + st0) = make_uint4(h2u(__floats2half2_rn(a00.x, a00.y)), h2u(__floats2half2_rn(a00.z, a00.w)),
                                           h2u(__floats2half2_rn(a01.x, a01.y)), h2u(__floats2half2_rn(a01.z, a01.w)));
        *(uint4*)(smem + st1) = make_uint4(h2u(__floats2half2_rn(a10.x, a10.y)), h2u(__floats2half2_rn(a10.z, a10.w)),
                                           h2u(__floats2half2_rn(a11.x, a11.y)), h2u(__floats2half2_rn(a11.z, a11.w)));
        cp_async16(sbB + st0, Bt + (size_t)(n0 + r0s) * K + k80 * 8);
        cp_async16(sbB + st1, Bt + (size_t)(n0 + r1s) * K + k81 * 8);
        CP_COMMIT();
        CP_WAIT0();
    }
    __syncthreads();

    for (int kt = 0; kt < nkt; kt++) {
        const int buf  = kt & 1;
        const int nbuf = 1 - buf;
        const bool nxt = (kt + 1) < nkt;

        float4 a00, a01, a10, a11;
        if (nxt) {
            const int k0 = (kt + 1) * 32;
            const float* ga0 = A + (size_t)(m0 + r0s) * K + k0 + k80 * 8;
            const float* ga1 = A + (size_t)(m0 + r1s) * K + k0 + k81 * 8;
            a00 = mv0 ? *(const float4*)ga0       : make_float4(0, 0, 0, 0);
            a01 = mv0 ? *(const float4*)(ga0 + 4) : make_float4(0, 0, 0, 0);
            a10 = mv1 ? *(const float4*)ga1       : make_float4(0, 0, 0, 0);
            a11 = mv1 ? *(const float4*)(ga1 + 4) : make_float4(0, 0, 0, 0);
            uint32_t bdst = sbB + nbuf * 8192u;
            cp_async16(bdst + st0, Bt + (size_t)(n0 + r0s) * K + k0 + k80 * 8);
            cp_async16(bdst + st1, Bt + (size_t)(n0 + r1s) * K + k0 + k81 * 8);
            CP_COMMIT();
        }

        // ---- compute on buf: 2 x k16 ----
        const uint32_t aB = sbA + buf * 8192u;
        const uint32_t bB = sbB + buf * 8192u;
#pragma unroll
        for (int kk = 0; kk < 2; kk++) {
            uint32_t af[2][4];
            uint32_t bf[8][2];
#pragma unroll
            for (int fm = 0; fm < 2; fm++) {
                uint32_t sl = (uint32_t)(2 * kk) * 128u + aLane + (uint32_t)(fm * 16);
                ldsm_x4(af[fm][0], af[fm][1], af[fm][2], af[fm][3], aB + sl * 16u);
            }
#pragma unroll
            for (int p = 0; p < 4; p++) {
                uint32_t sl = (uint32_t)(2 * kk) * 128u + bLane + (uint32_t)(p * 16);
                ldsm_x4(bf[2 * p][0], bf[2 * p][1], bf[2 * p + 1][0], bf[2 * p + 1][1],
                        bB + sl * 16u);
            }
#pragma unroll
            for (int fm = 0; fm < 2; fm++)
#pragma unroll
                for (int fn = 0; fn < 8; fn++) {
                    asm volatile(
                        "mma.sync.aligned.m16n8k16.row.col.f32.f16.f16.f32 "
                        "{%0,%1,%2,%3}, {%4,%5,%6,%7}, {%8,%9}, {%0,%1,%2,%3};"
                        : "+f"(acc[fm][fn][0]), "+f"(acc[fm][fn][1]),
                          "+f"(acc[fm][fn][2]), "+f"(acc[fm][fn][3])
                        : "r"(af[fm][0]), "r"(af[fm][1]), "r"(af[fm][2]), "r"(af[fm][3]),
                          "r"(bf[fn][0]), "r"(bf[fn][1]));
                }
        }

        if (nxt) {
            char* ad = smem + nbuf * 8192;
            *(uint4*)(ad + st0) = make_uint4(h2u(__floats2half2_rn(a00.x, a00.y)), h2u(__floats2half2_rn(a00.z, a00.w)),
                                             h2u(__floats2half2_rn(a01.x, a01.y)), h2u(__floats2half2_rn(a01.z, a01.w)));
            *(uint4*)(ad + st1) = make_uint4(h2u(__floats2half2_rn(a10.x, a10.y)), h2u(__floats2half2_rn(a10.z, a10.w)),
                                             h2u(__floats2half2_rn(a11.x, a11.y)), h2u(__floats2half2_rn(a11.z, a11.w)));
            CP_WAIT0();
        }
        __syncthreads();
    }

    // ---- epilogue: scale by dinv(row) = rsqrt(cnt+1), store ----
#pragma unroll
    for (int fm = 0; fm < 2; fm++) {
        int r0 = m0 + wm * 32 + fm * 16 + g;
        int r1 = r0 + 8;
        float d0 = (r0 < M) ? rsqrtf((float)__ldg(&cnt[r0]) + 1.0f) : 0.0f;
        float d1 = (r1 < M) ? rsqrtf((float)__ldg(&cnt[r1]) + 1.0f) : 0.0f;
#pragma unroll
        for (int fn = 0; fn < 8; fn++) {
            int col = n0 + wn * 64 + fn * 8 + c * 2;
            if (r0 < M)
                *(float2*)&Hs[(size_t)r0 * N + col] = make_float2(acc[fm][fn][0] * d0, acc[fm][fn][1] * d0);
            if (r1 < M)
                *(float2*)&Hs[(size_t)r1 * N + col] = make_float2(acc[fm][fn][2] * d1, acc[fm][fn][3] * d1);
        }
    }
}

// ---------------------------------------------------------------------------
// pull aggregation (chunked): thread = (dst, f4-in-chunk); hs pre-scaled.
// ---------------------------------------------------------------------------
template <int F4TOT, int F4C>
__global__ void k_pull_c(const int* __restrict__ rowp, const int* __restrict__ colA,
                         const float* __restrict__ hs, const float* __restrict__ dinv,
                         const float* __restrict__ bias, float* __restrict__ out,
                         int n, int fbase) {
    int idx = blockIdx.x * blockDim.x + threadIdx.x;
    int dst = idx / F4C;
    int j   = idx % F4C;
    if (dst >= n) return;
    int f4 = fbase + j;
    const float4* h4 = (const float4*)hs;
    float4 acc = h4[(size_t)dst * F4TOT + f4];   // self loop (hs already *dinv[src])
    int e0 = __ldg(&rowp[dst]);
    int e1 = __ldg(&rowp[dst + 1]);
    for (int e = e0; e < e1; e++) {
        int s = __ldg(&colA[e]);
        float4 v = h4[(size_t)s * F4TOT + f4];
        acc.x += v.x; acc.y += v.y; acc.z += v.z; acc.w += v.w;
    }
    float d = dinv[dst];
    float4 bb = ((const float4*)bias)[f4];
    float4 o = make_float4(bb.x + acc.x * d, bb.y + acc.y * d,
                           bb.z + acc.z * d, bb.w + acc.w * d);
    __stcs(&((float4*)out)[(size_t)dst * F4TOT + f4], o);
}

// ---------------------------------------------------------------------------
extern "C" void kernel_launch(void* const* d_in, const int* in_sizes, int n_in,
                              void* d_out, int out_size) {
    const float* x   = (const float*)d_in[0];
    const void*  ei  = d_in[1];
    const float* W1  = (const float*)d_in[3];
    const float* b1  = (const float*)d_in[4];
    const float* W2  = (const float*)d_in[5];
    const float* b2  = (const float*)d_in[6];
    float*       out = (float*)d_out;

    const long long nelem = (long long)in_sizes[1];
    const long long E     = nelem / 2;
    const int dhid        = in_sizes[4];         // 512
    const int dout        = in_sizes[6];         // 128
    const int din         = in_sizes[3] / dhid;  // 512
    const int n           = in_sizes[0] / din;   // 100000

    float *dinv_p, *h_p, *agg_p;
    __half *wt1_p, *wt2_p;
    int *cnt_p, *rowp_p, *cur_p, *col_p, *bsum_p;
    cudaGetSymbolAddress((void**)&dinv_p, g_dinv);
    cudaGetSymbolAddress((void**)&h_p,    g_h);
    cudaGetSymbolAddress((void**)&agg_p,  g_agg);
    cudaGetSymbolAddress((void**)&wt1_p,  g_wt1);
    cudaGetSymbolAddress((void**)&wt2_p,  g_wt2);
    cudaGetSymbolAddress((void**)&cnt_p,  g_cnt);
    cudaGetSymbolAddress((void**)&rowp_p, g_rowp);
    cudaGetSymbolAddress((void**)&cur_p,  g_cur);
    cudaGetSymbolAddress((void**)&col_p,  g_col);
    cudaGetSymbolAddress((void**)&bsum_p, g_bsum);

    const int eb   = (int)((E + 255) / 256);
    const int nb   = (n + 255) / 256;
    const int nblk = (n + 1023) / 1024;

    // 1: zero cnt + dtype detect
    k_init<<<nb, 256>>>(ei, nelem, n, cnt_p);
    // 2: W1^T fp16
    {
        dim3 grid(dhid / 32, din / 32), blk(32, 8);
        k_transpose_h<<<grid, blk>>>(W1, wt1_p, din, dhid);
    }
    // 3: degree histogram
    k_hist<<<eb, 256>>>(ei, E, cnt_p);
    // 4: GEMM1 (fp16 mma) -- profiled slot
    {
        dim3 grid(dhid / 128, (n + 127) / 128);
        k_gemm_h<<<grid, 256>>>(x, wt1_p, cnt_p, h_p, n, dhid, din);
    }
    // 5: W2^T fp16
    {
        dim3 grid(dout / 32, dhid / 32), blk(32, 8);
        k_transpose_h<<<grid, blk>>>(W2, wt2_p, dhid, dout);
    }
    // 6-10: CSR build
    k_scan_blk<<<nblk, 1024>>>(cnt_p, rowp_p, bsum_p, n);
    k_scan_top<<<1, 1024>>>(bsum_p, nblk);
    k_scan_add<<<(n + 256) / 256, 256>>>(rowp_p, bsum_p, n, nblk);
    k_dinv_cursor<<<nb, 256>>>(cnt_p, rowp_p, dinv_p, cur_p, n);
    k_scatter<<<eb, 256>>>(ei, E, cur_p, col_p);

    // layer-1 pull: 4 feature-chunk passes (51 MB gather footprint each)
    int tot = n * 32;
    for (int cidx = 0; cidx < 4; cidx++) {
        k_pull_c<128, 32><<<(tot + 255) / 256, 256>>>(rowp_p, col_p, h_p, dinv_p,
                                                      b1, agg_p, n, cidx * 32);
    }

    // layer 2
    {
        dim3 grid(dout / 128, (n + 127) / 128);
        k_gemm_h<<<grid, 256>>>(agg_p, wt2_p, cnt_p, h_p, n, dout, dhid);
        k_pull_c<32, 32><<<(tot + 255) / 256, 256>>>(rowp_p, col_p, h_p, dinv_p,
                                                     b2, out, n, 0);
    }

    (void)n_in; (void)out_size;
}

// round 9
// speedup vs baseline: 1.2712x; 1.1322x over previous
#include <cuda_runtime.h>
#include <cuda_fp16.h>
#include <stdint.h>

// ---------------------------------------------------------------------------
// GCN 2-layer, fp16 tensor-core GEMMs (m16n8k16, fp32 accum), fp16 feature
// buffers, CSR pull aggregation.
//   h16   = xh @ W1^T                (raw fp16)
//   agg16 = b1 + dinv*(h16*dinv_d + sum h16[src]*dinv_s)     (pull1, fp16 out)
//   hs2   = (agg16 @ W2^T) * dinv[row]                        (fp32)
//   out   = b2 + dinv*(hs2_self + sum hs2[src])               (pull2, fp32)
// ---------------------------------------------------------------------------

#define MAXN 100352
#define MAXE 1048576

__device__ __half g_xh[(size_t)MAXN * 512];    // x in fp16
__device__ __half g_h16[(size_t)MAXN * 512];   // layer-1 GEMM out (raw)
__device__ __half g_agg16[(size_t)MAXN * 512]; // layer-1 aggregated
__device__ float  g_hs2[(size_t)MAXN * 128];   // layer-2 GEMM out (dinv-scaled)
__device__ __half g_wt1[(size_t)512 * 512];    // W1^T fp16 [n][k]
__device__ __half g_wt2[(size_t)128 * 512];    // W2^T fp16 [n][k]
__device__ float  g_dinv[MAXN];
__device__ int    g_cnt[MAXN];
__device__ int    g_rowp[MAXN + 1];
__device__ int    g_cur[MAXN];
__device__ int    g_col[MAXE];
__device__ int    g_bsum[1025];
__device__ int    g_is64;

// ------------------------------- helpers -----------------------------------
__device__ __forceinline__ uint32_t smem_u32(const void* p) {
    uint32_t a;
    asm("{ .reg .u64 t; cvta.to.shared.u64 t, %1; cvt.u32.u64 %0, t; }" : "=r"(a) : "l"(p));
    return a;
}
__device__ __forceinline__ void ldsm_x4(uint32_t& r0, uint32_t& r1, uint32_t& r2, uint32_t& r3,
                                        uint32_t addr) {
    asm volatile("ldmatrix.sync.aligned.m8n8.x4.shared.b16 {%0,%1,%2,%3}, [%4];"
                 : "=r"(r0), "=r"(r1), "=r"(r2), "=r"(r3) : "r"(addr));
}
__device__ __forceinline__ void cp_async16(uint32_t dst, const void* src) {
    asm volatile("cp.async.ca.shared.global [%0], [%1], 16;" :: "r"(dst), "l"(src) : "memory");
}
#define CP_COMMIT() asm volatile("cp.async.commit_group;" ::: "memory")
#define CP_WAIT0()  asm volatile("cp.async.wait_group 0;" ::: "memory")

#define MMA16816(acc, af, bf)                                                  \
    asm volatile(                                                              \
        "mma.sync.aligned.m16n8k16.row.col.f32.f16.f16.f32 "                   \
        "{%0,%1,%2,%3}, {%4,%5,%6,%7}, {%8,%9}, {%0,%1,%2,%3};"                \
        : "+f"((acc)[0]), "+f"((acc)[1]), "+f"((acc)[2]), "+f"((acc)[3])       \
        : "r"((af)[0]), "r"((af)[1]), "r"((af)[2]), "r"((af)[3]),              \
          "r"((bf)[0]), "r"((bf)[1]))

__device__ __forceinline__ long long edge_at(const void* ei, long long idx, int is64) {
    if (is64) return ((const long long*)ei)[idx];
    return (long long)((const int*)ei)[idx];
}

// ---------------------------------------------------------------------------
// 1: x -> fp16 (zero-pad rows >= n), zero cnt, dtype detect
// ---------------------------------------------------------------------------
__global__ void k_xcvt_init(const float* __restrict__ x, const void* ei,
                            long long nelem, int n, __half* __restrict__ xh,
                            int* __restrict__ cnt) {
    int gid = blockIdx.x * blockDim.x + threadIdx.x;   // one 8-elem unit
    const int total = MAXN * 64;
    if (gid < total) {
        int row = gid >> 6, u = gid & 63;
        uint4 o;
        if (row < n) {
            const float4 v0 = *(const float4*)&x[(size_t)row * 512 + u * 8];
            const float4 v1 = *(const float4*)&x[(size_t)row * 512 + u * 8 + 4];
            __half2 h0 = __floats2half2_rn(v0.x, v0.y);
            __half2 h1 = __floats2half2_rn(v0.z, v0.w);
            __half2 h2 = __floats2half2_rn(v1.x, v1.y);
            __half2 h3 = __floats2half2_rn(v1.z, v1.w);
            o = make_uint4(*(uint32_t*)&h0, *(uint32_t*)&h1, *(uint32_t*)&h2, *(uint32_t*)&h3);
        } else {
            o = make_uint4(0, 0, 0, 0);
        }
        *(uint4*)&xh[(size_t)gid * 8] = o;
    }
    if (gid < n) cnt[gid] = 0;
    if (gid == 0) {
        const long long* p = (const long long*)ei;
        long long m = 64;
        if (m > nelem / 2) m = nelem / 2;
        int is64 = 1;
        for (long long j = 0; j < m; j++) {
            long long v = p[j];
            if (v < 0 || v >= (long long)n) { is64 = 0; break; }
        }
        g_is64 = is64;
    }
}

// W [K,N] fp32 -> Wt [N,K] fp16
__global__ void k_transpose_h(const float* __restrict__ W, __half* __restrict__ Wt, int K, int N) {
    __shared__ float tile[32][33];
    int k0 = blockIdx.y * 32, n0 = blockIdx.x * 32;
    int tx = threadIdx.x, ty = threadIdx.y;  // 32 x 8
    for (int j = 0; j < 32; j += 8)
        tile[ty + j][tx] = W[(size_t)(k0 + ty + j) * N + n0 + tx];
    __syncthreads();
    for (int j = 0; j < 32; j += 8)
        Wt[(size_t)(n0 + ty + j) * K + k0 + tx] = __float2half_rn(tile[tx][ty + j]);
}

__global__ void k_hist(const void* __restrict__ ei, long long E, int* __restrict__ cnt) {
    long long i = (long long)blockIdx.x * blockDim.x + threadIdx.x;
    if (i >= E) return;
    int d = (int)edge_at(ei, E + i, g_is64);
    atomicAdd(&cnt[d], 1);
}

__global__ void k_scan_blk(const int* __restrict__ cnt, int* __restrict__ rowp,
                           int* __restrict__ bsum, int n) {
    __shared__ int warpsum[32];
    const int t = threadIdx.x, lane = t & 31, w = t >> 5;
    int i = blockIdx.x * 1024 + t;
    int v = (i < n) ? cnt[i] : 0;
    int x = v;
#pragma unroll
    for (int off = 1; off < 32; off <<= 1) {
        int y = __shfl_up_sync(0xFFFFFFFFu, x, off);
        if (lane >= off) x += y;
    }
    if (lane == 31) warpsum[w] = x;
    __syncthreads();
    if (w == 0) {
        int s = warpsum[lane];
#pragma unroll
        for (int off = 1; off < 32; off <<= 1) {
            int y = __shfl_up_sync(0xFFFFFFFFu, s, off);
            if (lane >= off) s += y;
        }
        warpsum[lane] = s;
    }
    __syncthreads();
    int wpre = (w > 0) ? warpsum[w - 1] : 0;
    if (i < n) rowp[i] = x - v + wpre;
    if (t == 1023) bsum[blockIdx.x] = wpre + x;
}

__global__ void k_scan_top(int* __restrict__ bsum, int nb) {
    __shared__ int warpsum[32];
    const int t = threadIdx.x, lane = t & 31, w = t >> 5;
    int v = (t < nb) ? bsum[t] : 0;
    int x = v;
#pragma unroll
    for (int off = 1; off < 32; off <<= 1) {
        int y = __shfl_up_sync(0xFFFFFFFFu, x, off);
        if (lane >= off) x += y;
    }
    if (lane == 31) warpsum[w] = x;
    __syncthreads();
    if (w == 0) {
        int s = warpsum[lane];
#pragma unroll
        for (int off = 1; off < 32; off <<= 1) {
            int y = __shfl_up_sync(0xFFFFFFFFu, s, off);
            if (lane >= off) s += y;
        }
        warpsum[lane] = s;
    }
    __syncthreads();
    int wpre = (w > 0) ? warpsum[w - 1] : 0;
    if (t < nb) bsum[t] = x - v + wpre;
    if (t == 1023) bsum[nb] = warpsum[31];
}

__global__ void k_scan_add(int* __restrict__ rowp, const int* __restrict__ bsum, int n, int nb) {
    int i = blockIdx.x * blockDim.x + threadIdx.x;
    if (i < n) rowp[i] += bsum[i >> 10];
    if (i == n) rowp[n] = bsum[nb];
}

__global__ void k_dinv_cursor(const int* __restrict__ cnt, const int* __restrict__ rowp,
                              float* __restrict__ dinv, int* __restrict__ cur, int n) {
    int i = blockIdx.x * blockDim.x + threadIdx.x;
    if (i >= n) return;
    dinv[i] = rsqrtf((float)cnt[i] + 1.0f);
    cur[i]  = rowp[i];
}

__global__ void k_scatter(const void* __restrict__ ei, long long E,
                          int* __restrict__ cur, int* __restrict__ colA) {
    long long i = (long long)blockIdx.x * blockDim.x + threadIdx.x;
    if (i >= E) return;
    int is64 = g_is64;
    int s = (int)edge_at(ei, i, is64);
    int d = (int)edge_at(ei, E + i, is64);
    int pos = atomicAdd(&cur[d], 1);
    colA[pos] = s;
}

// ---------------------------------------------------------------------------
// GEMM1: H16[M,512] = A16[M,512] @ Wt[512,512]^T   (raw fp16 out)
// Block 128x256, warp 64x64 (8 warps 2x4), BK=32, both operands cp.async.
// smem layout: 16B slots, slot = k8*ROWS + row; A 512 slots, B 1024 slots.
// ---------------------------------------------------------------------------
__global__ __launch_bounds__(256, 1)
void k_gemm_big(const __half* __restrict__ A, const __half* __restrict__ Bt,
                __half* __restrict__ H)
{
    __shared__ __align__(16) char smem[49152];   // A 2x8KB @0, B 2x16KB @16384
    const uint32_t sbA = smem_u32(smem);
    const uint32_t sbB = sbA + 16384;

    const int t   = threadIdx.x;
    const int L   = t & 31;
    const int wid = t >> 5;
    const int wm  = wid >> 2;        // 0..1 -> 64 rows
    const int wn  = wid & 3;         // 0..3 -> 64 cols
    const int g   = L >> 2;
    const int c   = L & 3;
    const int m0  = blockIdx.y * 128;
    const int n0  = blockIdx.x * 256;

    // ldmatrix lane slot offsets
    const uint32_t aLane = ((uint32_t)((L >> 4) & 1)) * 128u
                         + (uint32_t)(wm * 64) + (uint32_t)(L & 7) + ((uint32_t)((L >> 3) & 1)) * 8u;
    const uint32_t bLane = ((uint32_t)((L >> 3) & 1)) * 256u
                         + (uint32_t)(wn * 64) + (uint32_t)(L & 7) + ((uint32_t)((L >> 4) & 1)) * 8u;

    // staging: A slots t, t+256 (k8 = s>>7, row = s&127); B slots t+256*i (k8 = s>>8, nrow = s&255)
    const int a_s0 = t, a_s1 = t + 256;
    const int a_r0 = a_s0 & 127, a_k0 = a_s0 >> 7;
    const int a_r1 = a_s1 & 127, a_k1 = a_s1 >> 7;

    float acc[4][8][4];
#pragma unroll
    for (int i = 0; i < 4; i++)
#pragma unroll
        for (int j = 0; j < 8; j++)
#pragma unroll
            for (int q = 0; q < 4; q++) acc[i][j][q] = 0.0f;

    // prologue
    {
        cp_async16(sbA + a_s0 * 16u, A + (size_t)(m0 + a_r0) * 512 + a_k0 * 8);
        cp_async16(sbA + a_s1 * 16u, A + (size_t)(m0 + a_r1) * 512 + a_k1 * 8);
#pragma unroll
        for (int i = 0; i < 4; i++) {
            int s = t + 256 * i;
            int nr = s & 255, k8 = s >> 8;
            cp_async16(sbB + s * 16u, Bt + (size_t)(n0 + nr) * 512 + k8 * 8);
        }
        CP_COMMIT();
        CP_WAIT0();
    }
    __syncthreads();

    for (int kt = 0; kt < 16; kt++) {
        const int buf  = kt & 1;
        const int nbuf = 1 - buf;
        const bool nxt = (kt + 1) < 16;

        if (nxt) {
            const int k0 = (kt + 1) * 32;
            cp_async16(sbA + nbuf * 8192u + a_s0 * 16u, A + (size_t)(m0 + a_r0) * 512 + k0 + a_k0 * 8);
            cp_async16(sbA + nbuf * 8192u + a_s1 * 16u, A + (size_t)(m0 + a_r1) * 512 + k0 + a_k1 * 8);
#pragma unroll
            for (int i = 0; i < 4; i++) {
                int s = t + 256 * i;
                int nr = s & 255, k8 = s >> 8;
                cp_async16(sbB + nbuf * 16384u + s * 16u, Bt + (size_t)(n0 + nr) * 512 + k0 + k8 * 8);
            }
            CP_COMMIT();
        }

        const uint32_t aB = sbA + buf * 8192u;
        const uint32_t bB = sbB + buf * 16384u;
#pragma unroll
        for (int kk = 0; kk < 2; kk++) {
            uint32_t af[4][4];
            uint32_t bf[8][2];
#pragma unroll
            for (int fm = 0; fm < 4; fm++)
                ldsm_x4(af[fm][0], af[fm][1], af[fm][2], af[fm][3],
                        aB + (aLane + (uint32_t)(kk * 256 + fm * 16)) * 16u);
#pragma unroll
            for (int p = 0; p < 4; p++)
                ldsm_x4(bf[2 * p][0], bf[2 * p][1], bf[2 * p + 1][0], bf[2 * p + 1][1],
                        bB + (bLane + (uint32_t)(kk * 512 + p * 16)) * 16u);
#pragma unroll
            for (int fm = 0; fm < 4; fm++)
#pragma unroll
                for (int fn = 0; fn < 8; fn++)
                    MMA16816(acc[fm][fn], af[fm], bf[fn]);
        }

        if (nxt) CP_WAIT0();
        __syncthreads();
    }

    // epilogue: raw fp16 store
#pragma unroll
    for (int fm = 0; fm < 4; fm++) {
        int r0 = m0 + wm * 64 + fm * 16 + g;
        int r1 = r0 + 8;
#pragma unroll
        for (int fn = 0; fn < 8; fn++) {
            int col = n0 + wn * 64 + fn * 8 + c * 2;
            __half2 v0 = __floats2half2_rn(acc[fm][fn][0], acc[fm][fn][1]);
            __half2 v1 = __floats2half2_rn(acc[fm][fn][2], acc[fm][fn][3]);
            *(__half2*)&H[(size_t)r0 * 512 + col] = v0;
            *(__half2*)&H[(size_t)r1 * 512 + col] = v1;
        }
    }
}

// ---------------------------------------------------------------------------
// GEMM2: Hs2[M,128] = (A16[M,512] @ Wt2[128,512]^T) * dinv[row]   (fp32 out)
// Block 128x128, warp 32x64 (8 warps 4x2), BK=32, both operands cp.async.
// ---------------------------------------------------------------------------
__global__ __launch_bounds__(256, 2)
void k_gemm2(const __half* __restrict__ A, const __half* __restrict__ Bt,
             const float* __restrict__ dinv, float* __restrict__ Hs, int M)
{
    __shared__ __align__(16) char smem[32768];   // A 2x8KB @0, B 2x8KB @16384
    const uint32_t sbA = smem_u32(smem);
    const uint32_t sbB = sbA + 16384;

    const int t   = threadIdx.x;
    const int L   = t & 31;
    const int wid = t >> 5;
    const int wm  = wid >> 1;        // 0..3
    const int wn  = wid & 1;         // 0..1
    const int g   = L >> 2;
    const int c   = L & 3;
    const int m0  = blockIdx.y * 128;

    const uint32_t aLane = ((uint32_t)((L >> 4) & 1)) * 128u
                         + (uint32_t)(wm * 32) + (uint32_t)(L & 7) + ((uint32_t)((L >> 3) & 1)) * 8u;
    const uint32_t bLane = ((uint32_t)((L >> 3) & 1)) * 128u
                         + (uint32_t)(wn * 64) + (uint32_t)(L & 7) + ((uint32_t)((L >> 4) & 1)) * 8u;

    const int s0 = t, s1 = t + 256;
    const int r0s = s0 & 127, k80 = s0 >> 7;
    const int r1s = s1 & 127, k81 = s1 >> 7;

    float acc[2][8][4];
#pragma unroll
    for (int i = 0; i < 2; i++)
#pragma unroll
        for (int j = 0; j < 8; j++)
#pragma unroll
            for (int q = 0; q < 4; q++) acc[i][j][q] = 0.0f;

    {
        cp_async16(sbA + s0 * 16u, A + (size_t)(m0 + r0s) * 512 + k80 * 8);
        cp_async16(sbA + s1 * 16u, A + (size_t)(m0 + r1s) * 512 + k81 * 8);
        cp_async16(sbB + s0 * 16u, Bt + (size_t)r0s * 512 + k80 * 8);
        cp_async16(sbB + s1 * 16u, Bt + (size_t)r1s * 512 + k81 * 8);
        CP_COMMIT();
        CP_WAIT0();
    }
    __syncthreads();

    for (int kt = 0; kt < 16; kt++) {
        const int buf  = kt & 1;
        const int nbuf = 1 - buf;
        const bool nxt = (kt + 1) < 16;

        if (nxt) {
            const int k0 = (kt + 1) * 32;
            cp_async16(sbA + nbuf * 8192u + s0 * 16u, A + (size_t)(m0 + r0s) * 512 + k0 + k80 * 8);
            cp_async16(sbA + nbuf * 8192u + s1 * 16u, A + (size_t)(m0 + r1s) * 512 + k0 + k81 * 8);
            cp_async16(sbB + nbuf * 8192u + s0 * 16u, Bt + (size_t)r0s * 512 + k0 + k80 * 8);
            cp_async16(sbB + nbuf * 8192u + s1 * 16u, Bt + (size_t)r1s * 512 + k0 + k81 * 8);
            CP_COMMIT();
        }

        const uint32_t aB = sbA + buf * 8192u;
        const uint32_t bB = sbB + buf * 8192u;
#pragma unroll
        for (int kk = 0; kk < 2; kk++) {
            uint32_t af[2][4];
            uint32_t bf[8][2];
#pragma unroll
            for (int fm = 0; fm < 2; fm++)
                ldsm_x4(af[fm][0], af[fm][1], af[fm][2], af[fm][3],
                        aB + (aLane + (uint32_t)(kk * 256 + fm * 16)) * 16u);
#pragma unroll
            for (int p = 0; p < 4; p++)
                ldsm_x4(bf[2 * p][0], bf[2 * p][1], bf[2 * p + 1][0], bf[2 * p + 1][1],
                        bB + (bLane + (uint32_t)(kk * 256 + p * 16)) * 16u);
#pragma unroll
            for (int fm = 0; fm < 2; fm++)
#pragma unroll
                for (int fn = 0; fn < 8; fn++)
                    MMA16816(acc[fm][fn], af[fm], bf[fn]);
        }

        if (nxt) CP_WAIT0();
        __syncthreads();
    }

#pragma unroll
    for (int fm = 0; fm < 2; fm++) {
        int r0 = m0 + wm * 32 + fm * 16 + g;
        int r1 = r0 + 8;
        float d0 = (r0 < M) ? dinv[r0] : 0.0f;
        float d1 = (r1 < M) ? dinv[r1] : 0.0f;
#pragma unroll
        for (int fn = 0; fn < 8; fn++) {
            int col = wn * 64 + fn * 8 + c * 2;
            if (r0 < M)
                *(float2*)&Hs[(size_t)r0 * 128 + col] = make_float2(acc[fm][fn][0] * d0, acc[fm][fn][1] * d0);
            if (r1 < M)
                *(float2*)&Hs[(size_t)r1 * 128 + col] = make_float2(acc[fm][fn][2] * d1, acc[fm][fn][3] * d1);
        }
    }
}

// ---------------------------------------------------------------------------
// pull1 (fp16 h, raw): agg16[d,f] = h16(b1[f] + dinv[d]*(h[d,f]*dinv[d] + sum h[s,f]*dinv[s]))
// thread = (dst, j 0..31), 4 halfs (8B) each; chunk = 128 feats.
// ---------------------------------------------------------------------------
__global__ void k_pull1_h(const int* __restrict__ rowp, const int* __restrict__ colA,
                          const __half* __restrict__ h16, const float* __restrict__ dinv,
                          const float* __restrict__ bias, __half* __restrict__ agg16,
                          int n, int cbase /* chunk * 32, in uint2 units */) {
    int idx = blockIdx.x * blockDim.x + threadIdx.x;
    int dst = idx >> 5;
    int j   = idx & 31;
    if (dst >= n) return;
    const uint2* h2p = (const uint2*)h16;       // 8B = 4 halfs; 128 uint2 per row
    const int u = cbase + j;                    // uint2 index within row

    float dd = __ldg(&dinv[dst]);
    uint2 sv = h2p[(size_t)dst * 128 + u];
    __half2 sa = *(__half2*)&sv.x, sb = *(__half2*)&sv.y;
    float2 f0 = __half22float2(sa), f1 = __half22float2(sb);
    float4 acc = make_float4(f0.x * dd, f0.y * dd, f1.x * dd, f1.y * dd);

    int e0 = __ldg(&rowp[dst]);
    int e1 = __ldg(&rowp[dst + 1]);
    for (int e = e0; e < e1; e++) {
        int s = __ldg(&colA[e]);
        float ds = __ldg(&dinv[s]);
        uint2 hv = h2p[(size_t)s * 128 + u];
        __half2 a = *(__half2*)&hv.x, b = *(__half2*)&hv.y;
        float2 g0 = __half22float2(a), g1 = __half22float2(b);
        acc.x += g0.x * ds; acc.y += g0.y * ds;
        acc.z += g1.x * ds; acc.w += g1.y * ds;
    }

    float4 bb = ((const float4*)bias)[u];
    __half2 o0 = __floats2half2_rn(bb.x + acc.x * dd, bb.y + acc.y * dd);
    __half2 o1 = __floats2half2_rn(bb.z + acc.z * dd, bb.w + acc.w * dd);
    uint2 ov = make_uint2(*(uint32_t*)&o0, *(uint32_t*)&o1);
    __stcs((uint2*)&((uint2*)agg16)[(size_t)dst * 128 + u], ov);
}

// ---------------------------------------------------------------------------
// pull2 (fp32, pre-scaled hs2): out = b2 + dinv[d]*(hs2[d] + sum hs2[s])
// ---------------------------------------------------------------------------
__global__ void k_pull2(const int* __restrict__ rowp, const int* __restrict__ colA,
                        const float* __restrict__ hs, const float* __restrict__ dinv,
                        const float* __restrict__ bias, float* __restrict__ out, int n) {
    int idx = blockIdx.x * blockDim.x + threadIdx.x;
    int dst = idx >> 5;
    int j   = idx & 31;
    if (dst >= n) return;
    const float4* h4 = (const float4*)hs;
    float4 acc = h4[(size_t)dst * 32 + j];
    int e0 = __ldg(&rowp[dst]);
    int e1 = __ldg(&rowp[dst + 1]);
    for (int e = e0; e < e1; e++) {
        int s = __ldg(&colA[e]);
        float4 v = h4[(size_t)s * 32 + j];
        acc.x += v.x; acc.y += v.y; acc.z += v.z; acc.w += v.w;
    }
    float d = dinv[dst];
    float4 bb = ((const float4*)bias)[j];
    float4 o = make_float4(bb.x + acc.x * d, bb.y + acc.y * d,
                           bb.z + acc.z * d, bb.w + acc.w * d);
    __stcs(&((float4*)out)[(size_t)dst * 32 + j], o);
}

// ---------------------------------------------------------------------------
extern "C" void kernel_launch(void* const* d_in, const int* in_sizes, int n_in,
                              void* d_out, int out_size) {
    const float* x   = (const float*)d_in[0];
    const void*  ei  = d_in[1];
    const float* W1  = (const float*)d_in[3];
    const float* b1  = (const float*)d_in[4];
    const float* W2  = (const float*)d_in[5];
    const float* b2  = (const float*)d_in[6];
    float*       out = (float*)d_out;

    const long long nelem = (long long)in_sizes[1];
    const long long E     = nelem / 2;
    const int dhid        = in_sizes[4];         // 512
    const int dout        = in_sizes[6];         // 128
    const int din         = in_sizes[3] / dhid;  // 512
    const int n           = in_sizes[0] / din;   // 100000

    __half *xh_p, *h16_p, *agg16_p, *wt1_p, *wt2_p;
    float *hs2_p, *dinv_p;
    int *cnt_p, *rowp_p, *cur_p, *col_p, *bsum_p;
    cudaGetSymbolAddress((void**)&xh_p,    g_xh);
    cudaGetSymbolAddress((void**)&h16_p,   g_h16);
    cudaGetSymbolAddress((void**)&agg16_p, g_agg16);
    cudaGetSymbolAddress((void**)&wt1_p,   g_wt1);
    cudaGetSymbolAddress((void**)&wt2_p,   g_wt2);
    cudaGetSymbolAddress((void**)&hs2_p,   g_hs2);
    cudaGetSymbolAddress((void**)&dinv_p,  g_dinv);
    cudaGetSymbolAddress((void**)&cnt_p,   g_cnt);
    cudaGetSymbolAddress((void**)&rowp_p,  g_rowp);
    cudaGetSymbolAddress((void**)&cur_p,   g_cur);
    cudaGetSymbolAddress((void**)&col_p,   g_col);
    cudaGetSymbolAddress((void**)&bsum_p,  g_bsum);

    const int eb   = (int)((E + 255) / 256);
    const int nb   = (n + 255) / 256;
    const int nblk = (n + 1023) / 1024;
    const int pull_blocks = (int)(((long long)n * 32 + 255) / 256);

    // 1: x->fp16 + zero cnt + detect
    k_xcvt_init<<<(MAXN * 64 + 255) / 256, 256>>>(x, ei, nelem, n, xh_p, cnt_p);
    // 2: W1^T fp16
    {
        dim3 grid(dhid / 32, din / 32), blk(32, 8);
        k_transpose_h<<<grid, blk>>>(W1, wt1_p, din, dhid);
    }
    // 3: degree histogram
    k_hist<<<eb, 256>>>(ei, E, cnt_p);
    // 4: GEMM1 (big fp16) -- profiled slot
    {
        dim3 grid(2, (n + 127) / 128);
        k_gemm_big<<<grid, 256>>>(xh_p, wt1_p, h16_p);
    }
    // 5: W2^T fp16
    {
        dim3 grid(dout / 32, dhid / 32), blk(32, 8);
        k_transpose_h<<<grid, blk>>>(W2, wt2_p, dhid, dout);
    }
    // 6-10: CSR build + dinv
    k_scan_blk<<<nblk, 1024>>>(cnt_p, rowp_p, bsum_p, n);
    k_scan_top<<<1, 1024>>>(bsum_p, nblk);
    k_scan_add<<<(n + 256) / 256, 256>>>(rowp_p, bsum_p, n, nblk);
    k_dinv_cursor<<<nb, 256>>>(cnt_p, rowp_p, dinv_p, cur_p, n);
    k_scatter<<<eb, 256>>>(ei, E, cur_p, col_p);

    // 11-14: layer-1 pull, 4 chunks of 128 feats (25.6 MB L2-resident each)
    for (int cidx = 0; cidx < 4; cidx++) {
        k_pull1_h<<<pull_blocks, 256>>>(rowp_p, col_p, h16_p, dinv_p,
                                        b1, agg16_p, n, cidx * 32);
    }

    // 15: GEMM2
    {
        dim3 grid(1, (n + 127) / 128);
        k_gemm2<<<grid, 256>>>(agg16_p, wt2_p, dinv_p, hs2_p, n);
    }
    // 16: layer-2 pull
    k_pull2<<<pull_blocks, 256>>>(rowp_p, col_p, hs2_p, dinv_p, b2, out, n);

    (void)n_in; (void)out_size;
}

// round 10
// speedup vs baseline: 1.3333x; 1.0489x over previous
#include <cuda_runtime.h>
#include <cuda_fp16.h>
#include <stdint.h>

// ---------------------------------------------------------------------------
// GCN 2-layer, fp16 tensor-core GEMMs (m16n8k16, fp32 accum), fp16 feature
// buffers, CSR pull aggregation.
//   h16   = xh @ W1^T                (raw fp16)
//   agg16 = b1 + dinv*(h16*dinv_d + sum h16[src]*dinv_s)     (pull1, fp16 out)
//   hs2   = (agg16 @ W2^T) * dinv[row]                        (fp32)
//   out   = b2 + dinv*(hs2_self + sum hs2[src])               (pull2, fp32)
// GEMM1: 512 threads, 3-stage cp.async multistage, warp tile 32x64.
// ---------------------------------------------------------------------------

#define MAXN 100352
#define MAXE 1048576

__device__ __half g_xh[(size_t)MAXN * 512];
__device__ __half g_h16[(size_t)MAXN * 512];
__device__ __half g_agg16[(size_t)MAXN * 512];
__device__ float  g_hs2[(size_t)MAXN * 128];
__device__ __half g_wt1[(size_t)512 * 512];
__device__ __half g_wt2[(size_t)128 * 512];
__device__ float  g_dinv[MAXN];
__device__ int    g_cnt[MAXN];
__device__ int    g_rowp[MAXN + 1];
__device__ int    g_cur[MAXN];
__device__ int    g_col[MAXE];
__device__ int    g_bsum[1025];
__device__ int    g_is64;

// ------------------------------- helpers -----------------------------------
__device__ __forceinline__ uint32_t smem_u32(const void* p) {
    uint32_t a;
    asm("{ .reg .u64 t; cvta.to.shared.u64 t, %1; cvt.u32.u64 %0, t; }" : "=r"(a) : "l"(p));
    return a;
}
__device__ __forceinline__ void ldsm_x4(uint32_t& r0, uint32_t& r1, uint32_t& r2, uint32_t& r3,
                                        uint32_t addr) {
    asm volatile("ldmatrix.sync.aligned.m8n8.x4.shared.b16 {%0,%1,%2,%3}, [%4];"
                 : "=r"(r0), "=r"(r1), "=r"(r2), "=r"(r3) : "r"(addr));
}
__device__ __forceinline__ void cp_async16(uint32_t dst, const void* src) {
    asm volatile("cp.async.ca.shared.global [%0], [%1], 16;" :: "r"(dst), "l"(src) : "memory");
}
#define CP_COMMIT() asm volatile("cp.async.commit_group;" ::: "memory")
#define CP_WAIT0()  asm volatile("cp.async.wait_group 0;" ::: "memory")
#define CP_WAIT1()  asm volatile("cp.async.wait_group 1;" ::: "memory")

#define MMA16816(acc, af, bf)                                                  \
    asm volatile(                                                              \
        "mma.sync.aligned.m16n8k16.row.col.f32.f16.f16.f32 "                   \
        "{%0,%1,%2,%3}, {%4,%5,%6,%7}, {%8,%9}, {%0,%1,%2,%3};"                \
        : "+f"((acc)[0]), "+f"((acc)[1]), "+f"((acc)[2]), "+f"((acc)[3])       \
        : "r"((af)[0]), "r"((af)[1]), "r"((af)[2]), "r"((af)[3]),              \
          "r"((bf)[0]), "r"((bf)[1]))

__device__ __forceinline__ long long edge_at(const void* ei, long long idx, int is64) {
    if (is64) return ((const long long*)ei)[idx];
    return (long long)((const int*)ei)[idx];
}

// ---------------------------------------------------------------------------
// 1: x -> fp16 (zero-pad rows >= n), zero cnt, dtype detect
// ---------------------------------------------------------------------------
__global__ void k_xcvt_init(const float* __restrict__ x, const void* ei,
                            long long nelem, int n, __half* __restrict__ xh,
                            int* __restrict__ cnt) {
    int gid = blockIdx.x * blockDim.x + threadIdx.x;
    const int total = MAXN * 64;
    if (gid < total) {
        int row = gid >> 6, u = gid & 63;
        uint4 o;
        if (row < n) {
            const float4 v0 = *(const float4*)&x[(size_t)row * 512 + u * 8];
            const float4 v1 = *(const float4*)&x[(size_t)row * 512 + u * 8 + 4];
            __half2 h0 = __floats2half2_rn(v0.x, v0.y);
            __half2 h1 = __floats2half2_rn(v0.z, v0.w);
            __half2 h2 = __floats2half2_rn(v1.x, v1.y);
            __half2 h3 = __floats2half2_rn(v1.z, v1.w);
            o = make_uint4(*(uint32_t*)&h0, *(uint32_t*)&h1, *(uint32_t*)&h2, *(uint32_t*)&h3);
        } else {
            o = make_uint4(0, 0, 0, 0);
        }
        *(uint4*)&xh[(size_t)gid * 8] = o;
    }
    if (gid < n) cnt[gid] = 0;
    if (gid == 0) {
        const long long* p = (const long long*)ei;
        long long m = 64;
        if (m > nelem / 2) m = nelem / 2;
        int is64 = 1;
        for (long long j = 0; j < m; j++) {
            long long v = p[j];
            if (v < 0 || v >= (long long)n) { is64 = 0; break; }
        }
        g_is64 = is64;
    }
}

// W [K,N] fp32 -> Wt [N,K] fp16
__global__ void k_transpose_h(const float* __restrict__ W, __half* __restrict__ Wt, int K, int N) {
    __shared__ float tile[32][33];
    int k0 = blockIdx.y * 32, n0 = blockIdx.x * 32;
    int tx = threadIdx.x, ty = threadIdx.y;  // 32 x 8
    for (int j = 0; j < 32; j += 8)
        tile[ty + j][tx] = W[(size_t)(k0 + ty + j) * N + n0 + tx];
    __syncthreads();
    for (int j = 0; j < 32; j += 8)
        Wt[(size_t)(n0 + ty + j) * K + k0 + tx] = __float2half_rn(tile[tx][ty + j]);
}

__global__ void k_hist(const void* __restrict__ ei, long long E, int* __restrict__ cnt) {
    long long i = (long long)blockIdx.x * blockDim.x + threadIdx.x;
    if (i >= E) return;
    int d = (int)edge_at(ei, E + i, g_is64);
    atomicAdd(&cnt[d], 1);
}

__global__ void k_scan_blk(const int* __restrict__ cnt, int* __restrict__ rowp,
                           int* __restrict__ bsum, int n) {
    __shared__ int warpsum[32];
    const int t = threadIdx.x, lane = t & 31, w = t >> 5;
    int i = blockIdx.x * 1024 + t;
    int v = (i < n) ? cnt[i] : 0;
    int x = v;
#pragma unroll
    for (int off = 1; off < 32; off <<= 1) {
        int y = __shfl_up_sync(0xFFFFFFFFu, x, off);
        if (lane >= off) x += y;
    }
    if (lane == 31) warpsum[w] = x;
    __syncthreads();
    if (w == 0) {
        int s = warpsum[lane];
#pragma unroll
        for (int off = 1; off < 32; off <<= 1) {
            int y = __shfl_up_sync(0xFFFFFFFFu, s, off);
            if (lane >= off) s += y;
        }
        warpsum[lane] = s;
    }
    __syncthreads();
    int wpre = (w > 0) ? warpsum[w - 1] : 0;
    if (i < n) rowp[i] = x - v + wpre;
    if (t == 1023) bsum[blockIdx.x] = wpre + x;
}

__global__ void k_scan_top(int* __restrict__ bsum, int nb) {
    __shared__ int warpsum[32];
    const int t = threadIdx.x, lane = t & 31, w = t >> 5;
    int v = (t < nb) ? bsum[t] : 0;
    int x = v;
#pragma unroll
    for (int off = 1; off < 32; off <<= 1) {
        int y = __shfl_up_sync(0xFFFFFFFFu, x, off);
        if (lane >= off) x += y;
    }
    if (lane == 31) warpsum[w] = x;
    __syncthreads();
    if (w == 0) {
        int s = warpsum[lane];
#pragma unroll
        for (int off = 1; off < 32; off <<= 1) {
            int y = __shfl_up_sync(0xFFFFFFFFu, s, off);
            if (lane >= off) s += y;
        }
        warpsum[lane] = s;
    }
    __syncthreads();
    int wpre = (w > 0) ? warpsum[w - 1] : 0;
    if (t < nb) bsum[t] = x - v + wpre;
    if (t == 1023) bsum[nb] = warpsum[31];
}

__global__ void k_scan_add(int* __restrict__ rowp, const int* __restrict__ bsum, int n, int nb) {
    int i = blockIdx.x * blockDim.x + threadIdx.x;
    if (i < n) rowp[i] += bsum[i >> 10];
    if (i == n) rowp[n] = bsum[nb];
}

__global__ void k_dinv_cursor(const int* __restrict__ cnt, const int* __restrict__ rowp,
                              float* __restrict__ dinv, int* __restrict__ cur, int n) {
    int i = blockIdx.x * blockDim.x + threadIdx.x;
    if (i >= n) return;
    dinv[i] = rsqrtf((float)cnt[i] + 1.0f);
    cur[i]  = rowp[i];
}

__global__ void k_scatter(const void* __restrict__ ei, long long E,
                          int* __restrict__ cur, int* __restrict__ colA) {
    long long i = (long long)blockIdx.x * blockDim.x + threadIdx.x;
    if (i >= E) return;
    int is64 = g_is64;
    int s = (int)edge_at(ei, i, is64);
    int d = (int)edge_at(ei, E + i, is64);
    int pos = atomicAdd(&cur[d], 1);
    colA[pos] = s;
}

// ---------------------------------------------------------------------------
// GEMM1: H16[M,512] = A16[M,512] @ Wt[512,512]^T  (raw fp16 out)
// Block 128x256, 512 threads (16 warps 4x4), warp tile 32x64, BK=32,
// 3-stage cp.async multistage. Dynamic smem: 3*(8KB A + 16KB B) = 72KB.
// smem layout per stage: 16B slots, slot = k8*ROWS + row.
// ---------------------------------------------------------------------------
#define G1_SMEM (3 * (8192 + 16384))

__global__ __launch_bounds__(512, 1)
void k_gemm_big(const __half* __restrict__ A, const __half* __restrict__ Bt,
                __half* __restrict__ H)
{
    extern __shared__ __align__(16) char smem[];   // A stages @0, B stages @24576
    const uint32_t sbA = smem_u32(smem);
    const uint32_t sbB = sbA + 3 * 8192;

    const int t   = threadIdx.x;
    const int L   = t & 31;
    const int wid = t >> 5;
    const int wm  = wid >> 2;        // 0..3 -> 32 rows
    const int wn  = wid & 3;         // 0..3 -> 64 cols
    const int g   = L >> 2;
    const int c   = L & 3;
    const int m0  = blockIdx.y * 128;
    const int n0  = blockIdx.x * 256;

    // ldmatrix lane slot offsets (A: 128 slots per k8; B: 256 slots per k8)
    const uint32_t aLane = ((uint32_t)((L >> 4) & 1)) * 128u
                         + (uint32_t)(wm * 32) + (uint32_t)(L & 7) + ((uint32_t)((L >> 3) & 1)) * 8u;
    const uint32_t bLane = ((uint32_t)((L >> 3) & 1)) * 256u
                         + (uint32_t)(wn * 64) + (uint32_t)(L & 7) + ((uint32_t)((L >> 4) & 1)) * 8u;

    // staging: A 512 slots -> 1/thread; B 1024 slots -> 2/thread
    const int a_row = t & 127, a_k8 = t >> 7;
    const int b_r0  = t & 255, b_k0 = t >> 8;           // slot t
    const int b_r1  = b_r0,    b_k1 = b_k0 + 2;         // slot t+512

    float acc[2][8][4];
#pragma unroll
    for (int i = 0; i < 2; i++)
#pragma unroll
        for (int j = 0; j < 8; j++)
#pragma unroll
            for (int q = 0; q < 4; q++) acc[i][j][q] = 0.0f;

    // stage issue helper
    auto issue = [&](int kt) {
        const int stg = kt % 3;
        const int k0 = kt * 32;
        cp_async16(sbA + stg * 8192u + (uint32_t)t * 16u,
                   A + (size_t)(m0 + a_row) * 512 + k0 + a_k8 * 8);
        uint32_t bbase = sbB + stg * 16384u;
        cp_async16(bbase + (uint32_t)t * 16u,
                   Bt + (size_t)(n0 + b_r0) * 512 + k0 + b_k0 * 8);
        cp_async16(bbase + (uint32_t)(t + 512) * 16u,
                   Bt + (size_t)(n0 + b_r1) * 512 + k0 + b_k1 * 8);
        CP_COMMIT();
    };

    issue(0);
    issue(1);

    for (int kt = 0; kt < 16; kt++) {
        if (kt + 1 < 16) { CP_WAIT1(); } else { CP_WAIT0(); }
        __syncthreads();

        const int stg = kt % 3;
        const uint32_t aB = sbA + stg * 8192u;
        const uint32_t bB = sbB + stg * 16384u;
#pragma unroll
        for (int kk = 0; kk < 2; kk++) {
            uint32_t af[2][4];
            uint32_t bf[8][2];
#pragma unroll
            for (int fm = 0; fm < 2; fm++)
                ldsm_x4(af[fm][0], af[fm][1], af[fm][2], af[fm][3],
                        aB + (aLane + (uint32_t)(kk * 256 + fm * 16)) * 16u);
#pragma unroll
            for (int p = 0; p < 4; p++)
                ldsm_x4(bf[2 * p][0], bf[2 * p][1], bf[2 * p + 1][0], bf[2 * p + 1][1],
                        bB + (bLane + (uint32_t)(kk * 512 + p * 16)) * 16u);
#pragma unroll
            for (int fm = 0; fm < 2; fm++)
#pragma unroll
                for (int fn = 0; fn < 8; fn++)
                    MMA16816(acc[fm][fn], af[fm], bf[fn]);
        }

        if (kt + 2 < 16) issue(kt + 2);
        __syncthreads();
    }

    // epilogue: raw fp16 store (rows padded in xh/h16, no M guard needed)
#pragma unroll
    for (int fm = 0; fm < 2; fm++) {
        int r0 = m0 + wm * 32 + fm * 16 + g;
        int r1 = r0 + 8;
#pragma unroll
        for (int fn = 0; fn < 8; fn++) {
            int col = n0 + wn * 64 + fn * 8 + c * 2;
            __half2 v0 = __floats2half2_rn(acc[fm][fn][0], acc[fm][fn][1]);
            __half2 v1 = __floats2half2_rn(acc[fm][fn][2], acc[fm][fn][3]);
            *(__half2*)&H[(size_t)r0 * 512 + col] = v0;
            *(__half2*)&H[(size_t)r1 * 512 + col] = v1;
        }
    }
}

// ---------------------------------------------------------------------------
// GEMM2: Hs2[M,128] = (A16[M,512] @ Wt2[128,512]^T) * dinv[row]  (fp32 out)
// Block 128x128, warp 32x64 (8 warps 4x2), BK=32, double-buffered (proven R9).
// ---------------------------------------------------------------------------
__global__ __launch_bounds__(256, 2)
void k_gemm2(const __half* __restrict__ A, const __half* __restrict__ Bt,
             const float* __restrict__ dinv, float* __restrict__ Hs, int M)
{
    __shared__ __align__(16) char smem[32768];
    const uint32_t sbA = smem_u32(smem);
    const uint32_t sbB = sbA + 16384;

    const int t   = threadIdx.x;
    const int L   = t & 31;
    const int wid = t >> 5;
    const int wm  = wid >> 1;
    const int wn  = wid & 1;
    const int g   = L >> 2;
    const int c   = L & 3;
    const int m0  = blockIdx.y * 128;

    const uint32_t aLane = ((uint32_t)((L >> 4) & 1)) * 128u
                         + (uint32_t)(wm * 32) + (uint32_t)(L & 7) + ((uint32_t)((L >> 3) & 1)) * 8u;
    const uint32_t bLane = ((uint32_t)((L >> 3) & 1)) * 128u
                         + (uint32_t)(wn * 64) + (uint32_t)(L & 7) + ((uint32_t)((L >> 4) & 1)) * 8u;

    const int s0 = t, s1 = t + 256;
    const int r0s = s0 & 127, k80 = s0 >> 7;
    const int r1s = s1 & 127, k81 = s1 >> 7;

    float acc[2][8][4];
#pragma unroll
    for (int i = 0; i < 2; i++)
#pragma unroll
        for (int j = 0; j < 8; j++)
#pragma unroll
            for (int q = 0; q < 4; q++) acc[i][j][q] = 0.0f;

    {
        cp_async16(sbA + s0 * 16u, A + (size_t)(m0 + r0s) * 512 + k80 * 8);
        cp_async16(sbA + s1 * 16u, A + (size_t)(m0 + r1s) * 512 + k81 * 8);
        cp_async16(sbB + s0 * 16u, Bt + (size_t)r0s * 512 + k80 * 8);
        cp_async16(sbB + s1 * 16u, Bt + (size_t)r1s * 512 + k81 * 8);
        CP_COMMIT();
        CP_WAIT0();
    }
    __syncthreads();

    for (int kt = 0; kt < 16; kt++) {
        const int buf  = kt & 1;
        const int nbuf = 1 - buf;
        const bool nxt = (kt + 1) < 16;

        if (nxt) {
            const int k0 = (kt + 1) * 32;
            cp_async16(sbA + nbuf * 8192u + s0 * 16u, A + (size_t)(m0 + r0s) * 512 + k0 + k80 * 8);
            cp_async16(sbA + nbuf * 8192u + s1 * 16u, A + (size_t)(m0 + r1s) * 512 + k0 + k81 * 8);
            cp_async16(sbB + nbuf * 8192u + s0 * 16u, Bt + (size_t)r0s * 512 + k0 + k80 * 8);
            cp_async16(sbB + nbuf * 8192u + s1 * 16u, Bt + (size_t)r1s * 512 + k0 + k81 * 8);
            CP_COMMIT();
        }

        const uint32_t aB = sbA + buf * 8192u;
        const uint32_t bB = sbB + buf * 8192u;
#pragma unroll
        for (int kk = 0; kk < 2; kk++) {
            uint32_t af[2][4];
            uint32_t bf[8][2];
#pragma unroll
            for (int fm = 0; fm < 2; fm++)
                ldsm_x4(af[fm][0], af[fm][1], af[fm][2], af[fm][3],
                        aB + (aLane + (uint32_t)(kk * 256 + fm * 16)) * 16u);
#pragma unroll
            for (int p = 0; p < 4; p++)
                ldsm_x4(bf[2 * p][0], bf[2 * p][1], bf[2 * p + 1][0], bf[2 * p + 1][1],
                        bB + (bLane + (uint32_t)(kk * 256 + p * 16)) * 16u);
#pragma unroll
            for (int fm = 0; fm < 2; fm++)
#pragma unroll
                for (int fn = 0; fn < 8; fn++)
                    MMA16816(acc[fm][fn], af[fm], bf[fn]);
        }

        if (nxt) CP_WAIT0();
        __syncthreads();
    }

#pragma unroll
    for (int fm = 0; fm < 2; fm++) {
        int r0 = m0 + wm * 32 + fm * 16 + g;
        int r1 = r0 + 8;
        float d0 = (r0 < M) ? dinv[r0] : 0.0f;
        float d1 = (r1 < M) ? dinv[r1] : 0.0f;
#pragma unroll
        for (int fn = 0; fn < 8; fn++) {
            int col = wn * 64 + fn * 8 + c * 2;
            if (r0 < M)
                *(float2*)&Hs[(size_t)r0 * 128 + col] = make_float2(acc[fm][fn][0] * d0, acc[fm][fn][1] * d0);
            if (r1 < M)
                *(float2*)&Hs[(size_t)r1 * 128 + col] = make_float2(acc[fm][fn][2] * d1, acc[fm][fn][3] * d1);
        }
    }
}

// ---------------------------------------------------------------------------
// pull1 (fp16): agg16[d,f] = h16(b1[f] + dinv[d]*(h[d,f]*dinv[d] + sum h[s,f]*dinv[s]))
// ---------------------------------------------------------------------------
__global__ void k_pull1_h(const int* __restrict__ rowp, const int* __restrict__ colA,
                          const __half* __restrict__ h16, const float* __restrict__ dinv,
                          const float* __restrict__ bias, __half* __restrict__ agg16,
                          int n, int cbase) {
    int idx = blockIdx.x * blockDim.x + threadIdx.x;
    int dst = idx >> 5;
    int j   = idx & 31;
    if (dst >= n) return;
    const uint2* h2p = (const uint2*)h16;
    const int u = cbase + j;

    float dd = __ldg(&dinv[dst]);
    uint2 sv = h2p[(size_t)dst * 128 + u];
    __half2 sa = *(__half2*)&sv.x, sb = *(__half2*)&sv.y;
    float2 f0 = __half22float2(sa), f1 = __half22float2(sb);
    float4 acc = make_float4(f0.x * dd, f0.y * dd, f1.x * dd, f1.y * dd);

    int e0 = __ldg(&rowp[dst]);
    int e1 = __ldg(&rowp[dst + 1]);
    for (int e = e0; e < e1; e++) {
        int s = __ldg(&colA[e]);
        float ds = __ldg(&dinv[s]);
        uint2 hv = h2p[(size_t)s * 128 + u];
        __half2 a = *(__half2*)&hv.x, b = *(__half2*)&hv.y;
        float2 g0 = __half22float2(a), g1 = __half22float2(b);
        acc.x += g0.x * ds; acc.y += g0.y * ds;
        acc.z += g1.x * ds; acc.w += g1.y * ds;
    }

    float4 bb = ((const float4*)bias)[u];
    __half2 o0 = __floats2half2_rn(bb.x + acc.x * dd, bb.y + acc.y * dd);
    __half2 o1 = __floats2half2_rn(bb.z + acc.z * dd, bb.w + acc.w * dd);
    uint2 ov = make_uint2(*(uint32_t*)&o0, *(uint32_t*)&o1);
    __stcs((uint2*)&((uint2*)agg16)[(size_t)dst * 128 + u], ov);
}

// ---------------------------------------------------------------------------
// pull2 (fp32): out = b2 + dinv[d]*(hs2[d] + sum hs2[s])
// ---------------------------------------------------------------------------
__global__ void k_pull2(const int* __restrict__ rowp, const int* __restrict__ colA,
                        const float* __restrict__ hs, const float* __restrict__ dinv,
                        const float* __restrict__ bias, float* __restrict__ out, int n) {
    int idx = blockIdx.x * blockDim.x + threadIdx.x;
    int dst = idx >> 5;
    int j   = idx & 31;
    if (dst >= n) return;
    const float4* h4 = (const float4*)hs;
    float4 acc = h4[(size_t)dst * 32 + j];
    int e0 = __ldg(&rowp[dst]);
    int e1 = __ldg(&rowp[dst + 1]);
    for (int e = e0; e < e1; e++) {
        int s = __ldg(&colA[e]);
        float4 v = h4[(size_t)s * 32 + j];
        acc.x += v.x; acc.y += v.y; acc.z += v.z; acc.w += v.w;
    }
    float d = dinv[dst];
    float4 bb = ((const float4*)bias)[j];
    float4 o = make_float4(bb.x + acc.x * d, bb.y + acc.y * d,
                           bb.z + acc.z * d, bb.w + acc.w * d);
    __stcs(&((float4*)out)[(size_t)dst * 32 + j], o);
}

// ---------------------------------------------------------------------------
extern "C" void kernel_launch(void* const* d_in, const int* in_sizes, int n_in,
                              void* d_out, int out_size) {
    const float* x   = (const float*)d_in[0];
    const void*  ei  = d_in[1];
    const float* W1  = (const float*)d_in[3];
    const float* b1  = (const float*)d_in[4];
    const float* W2  = (const float*)d_in[5];
    const float* b2  = (const float*)d_in[6];
    float*       out = (float*)d_out;

    const long long nelem = (long long)in_sizes[1];
    const long long E     = nelem / 2;
    const int dhid        = in_sizes[4];         // 512
    const int dout        = in_sizes[6];         // 128
    const int din         = in_sizes[3] / dhid;  // 512
    const int n           = in_sizes[0] / din;   // 100000

    __half *xh_p, *h16_p, *agg16_p, *wt1_p, *wt2_p;
    float *hs2_p, *dinv_p;
    int *cnt_p, *rowp_p, *cur_p, *col_p, *bsum_p;
    cudaGetSymbolAddress((void**)&xh_p,    g_xh);
    cudaGetSymbolAddress((void**)&h16_p,   g_h16);
    cudaGetSymbolAddress((void**)&agg16_p, g_agg16);
    cudaGetSymbolAddress((void**)&wt1_p,   g_wt1);
    cudaGetSymbolAddress((void**)&wt2_p,   g_wt2);
    cudaGetSymbolAddress((void**)&hs2_p,   g_hs2);
    cudaGetSymbolAddress((void**)&dinv_p,  g_dinv);
    cudaGetSymbolAddress((void**)&cnt_p,   g_cnt);
    cudaGetSymbolAddress((void**)&rowp_p,  g_rowp);
    cudaGetSymbolAddress((void**)&cur_p,   g_cur);
    cudaGetSymbolAddress((void**)&col_p,   g_col);
    cudaGetSymbolAddress((void**)&bsum_p,  g_bsum);

    static bool attr_set = false;
    if (!attr_set) {
        cudaFuncSetAttribute(k_gemm_big, cudaFuncAttributeMaxDynamicSharedMemorySize, G1_SMEM);
        attr_set = true;
    }

    const int eb   = (int)((E + 255) / 256);
    const int nb   = (n + 255) / 256;
    const int nblk = (n + 1023) / 1024;
    const int pull_blocks = (int)(((long long)n * 32 + 255) / 256);

    // 1: x->fp16 + zero cnt + detect
    k_xcvt_init<<<(MAXN * 64 + 255) / 256, 256>>>(x, ei, nelem, n, xh_p, cnt_p);
    // 2: W1^T fp16
    {
        dim3 grid(dhid / 32, din / 32), blk(32, 8);
        k_transpose_h<<<grid, blk>>>(W1, wt1_p, din, dhid);
    }
    // 3: degree histogram
    k_hist<<<eb, 256>>>(ei, E, cnt_p);
    // 4: GEMM1 (512-thread multistage) -- profiled slot
    {
        dim3 grid(2, (n + 127) / 128);
        k_gemm_big<<<grid, 512, G1_SMEM>>>(xh_p, wt1_p, h16_p);
    }
    // 5: W2^T fp16
    {
        dim3 grid(dout / 32, dhid / 32), blk(32, 8);
        k_transpose_h<<<grid, blk>>>(W2, wt2_p, dhid, dout);
    }
    // 6-10: CSR build + dinv
    k_scan_blk<<<nblk, 1024>>>(cnt_p, rowp_p, bsum_p, n);
    k_scan_top<<<1, 1024>>>(bsum_p, nblk);
    k_scan_add<<<(n + 256) / 256, 256>>>(rowp_p, bsum_p, n, nblk);
    k_dinv_cursor<<<nb, 256>>>(cnt_p, rowp_p, dinv_p, cur_p, n);
    k_scatter<<<eb, 256>>>(ei, E, cur_p, col_p);

    // 11-14: layer-1 pull, 4 chunks of 128 feats
    for (int cidx = 0; cidx < 4; cidx++) {
        k_pull1_h<<<pull_blocks, 256>>>(rowp_p, col_p, h16_p, dinv_p,
                                        b1, agg16_p, n, cidx * 32);
    }

    // 15: GEMM2
    {
        dim3 grid(1, (n + 127) / 128);
        k_gemm2<<<grid, 256>>>(agg16_p, wt2_p, dinv_p, hs2_p, n);
    }
    // 16: layer-2 pull
    k_pull2<<<pull_blocks, 256>>>(rowp_p, col_p, hs2_p, dinv_p, b2, out, n);

    (void)n_in; (void)out_size;
}

// round 11
// speedup vs baseline: 1.3507x; 1.0130x over previous
#include <cuda_runtime.h>
#include <cuda_fp16.h>
#include <stdint.h>

// ---------------------------------------------------------------------------
// GCN 2-layer, fp16 tensor-core GEMMs (m16n8k16, fp32 accum), fp16 feature
// buffers end-to-end, CSR pull aggregation.
//   h16   = xh @ W1^T                 (raw fp16)
//   agg16 = b1 + dinv*(h16*dinv_d + sum h16[src]*dinv_s)   (pull1, fp16 out)
//   hs2h  = (agg16 @ W2^T) * dinv[row]                      (fp16)
//   out   = b2 + dinv*(hs2h[d] + sum hs2h[src])             (pull2, fp32 out)
// ---------------------------------------------------------------------------

#define MAXN 100352
#define MAXE 1048576

__device__ __half g_xh[(size_t)MAXN * 512];
__device__ __half g_h16[(size_t)MAXN * 512];
__device__ __half g_agg16[(size_t)MAXN * 512];
__device__ __half g_hs2h[(size_t)MAXN * 128];
__device__ __half g_wt1[(size_t)512 * 512];
__device__ __half g_wt2[(size_t)128 * 512];
__device__ float  g_dinv[MAXN];
__device__ int    g_cnt[MAXN];
__device__ int    g_rowp[MAXN + 1];
__device__ int    g_cur[MAXN];
__device__ int    g_col[MAXE];
__device__ int    g_bsum[1025];
__device__ int    g_is64;

// ------------------------------- helpers -----------------------------------
__device__ __forceinline__ uint32_t smem_u32(const void* p) {
    uint32_t a;
    asm("{ .reg .u64 t; cvta.to.shared.u64 t, %1; cvt.u32.u64 %0, t; }" : "=r"(a) : "l"(p));
    return a;
}
__device__ __forceinline__ void ldsm_x4(uint32_t& r0, uint32_t& r1, uint32_t& r2, uint32_t& r3,
                                        uint32_t addr) {
    asm volatile("ldmatrix.sync.aligned.m8n8.x4.shared.b16 {%0,%1,%2,%3}, [%4];"
                 : "=r"(r0), "=r"(r1), "=r"(r2), "=r"(r3) : "r"(addr));
}
__device__ __forceinline__ void cp_async16(uint32_t dst, const void* src) {
    asm volatile("cp.async.ca.shared.global [%0], [%1], 16;" :: "r"(dst), "l"(src) : "memory");
}
#define CP_COMMIT() asm volatile("cp.async.commit_group;" ::: "memory")
#define CP_WAIT0()  asm volatile("cp.async.wait_group 0;" ::: "memory")
#define CP_WAIT1()  asm volatile("cp.async.wait_group 1;" ::: "memory")

#define MMA16816(acc, af, bf)                                                  \
    asm volatile(                                                              \
        "mma.sync.aligned.m16n8k16.row.col.f32.f16.f16.f32 "                   \
        "{%0,%1,%2,%3}, {%4,%5,%6,%7}, {%8,%9}, {%0,%1,%2,%3};"                \
        : "+f"((acc)[0]), "+f"((acc)[1]), "+f"((acc)[2]), "+f"((acc)[3])       \
        : "r"((af)[0]), "r"((af)[1]), "r"((af)[2]), "r"((af)[3]),              \
          "r"((bf)[0]), "r"((bf)[1]))

__device__ __forceinline__ long long edge_at(const void* ei, long long idx, int is64) {
    if (is64) return ((const long long*)ei)[idx];
    return (long long)((const int*)ei)[idx];
}

// ---------------------------------------------------------------------------
__global__ void k_xcvt_init(const float* __restrict__ x, const void* ei,
                            long long nelem, int n, __half* __restrict__ xh,
                            int* __restrict__ cnt) {
    int gid = blockIdx.x * blockDim.x + threadIdx.x;
    const int total = MAXN * 64;
    if (gid < total) {
        int row = gid >> 6, u = gid & 63;
        uint4 o;
        if (row < n) {
            const float4 v0 = *(const float4*)&x[(size_t)row * 512 + u * 8];
            const float4 v1 = *(const float4*)&x[(size_t)row * 512 + u * 8 + 4];
            __half2 h0 = __floats2half2_rn(v0.x, v0.y);
            __half2 h1 = __floats2half2_rn(v0.z, v0.w);
            __half2 h2 = __floats2half2_rn(v1.x, v1.y);
            __half2 h3 = __floats2half2_rn(v1.z, v1.w);
            o = make_uint4(*(uint32_t*)&h0, *(uint32_t*)&h1, *(uint32_t*)&h2, *(uint32_t*)&h3);
        } else {
            o = make_uint4(0, 0, 0, 0);
        }
        *(uint4*)&xh[(size_t)gid * 8] = o;
    }
    if (gid < n) cnt[gid] = 0;
    if (gid == 0) {
        const long long* p = (const long long*)ei;
        long long m = 64;
        if (m > nelem / 2) m = nelem / 2;
        int is64 = 1;
        for (long long j = 0; j < m; j++) {
            long long v = p[j];
            if (v < 0 || v >= (long long)n) { is64 = 0; break; }
        }
        g_is64 = is64;
    }
}

__global__ void k_transpose_h(const float* __restrict__ W, __half* __restrict__ Wt, int K, int N) {
    __shared__ float tile[32][33];
    int k0 = blockIdx.y * 32, n0 = blockIdx.x * 32;
    int tx = threadIdx.x, ty = threadIdx.y;  // 32 x 8
    for (int j = 0; j < 32; j += 8)
        tile[ty + j][tx] = W[(size_t)(k0 + ty + j) * N + n0 + tx];
    __syncthreads();
    for (int j = 0; j < 32; j += 8)
        Wt[(size_t)(n0 + ty + j) * K + k0 + tx] = __float2half_rn(tile[tx][ty + j]);
}

__global__ void k_hist(const void* __restrict__ ei, long long E, int* __restrict__ cnt) {
    long long i = (long long)blockIdx.x * blockDim.x + threadIdx.x;
    if (i >= E) return;
    int d = (int)edge_at(ei, E + i, g_is64);
    atomicAdd(&cnt[d], 1);
}

__global__ void k_scan_blk(const int* __restrict__ cnt, int* __restrict__ rowp,
                           int* __restrict__ bsum, int n) {
    __shared__ int warpsum[32];
    const int t = threadIdx.x, lane = t & 31, w = t >> 5;
    int i = blockIdx.x * 1024 + t;
    int v = (i < n) ? cnt[i] : 0;
    int x = v;
#pragma unroll
    for (int off = 1; off < 32; off <<= 1) {
        int y = __shfl_up_sync(0xFFFFFFFFu, x, off);
        if (lane >= off) x += y;
    }
    if (lane == 31) warpsum[w] = x;
    __syncthreads();
    if (w == 0) {
        int s = warpsum[lane];
#pragma unroll
        for (int off = 1; off < 32; off <<= 1) {
            int y = __shfl_up_sync(0xFFFFFFFFu, s, off);
            if (lane >= off) s += y;
        }
        warpsum[lane] = s;
    }
    __syncthreads();
    int wpre = (w > 0) ? warpsum[w - 1] : 0;
    if (i < n) rowp[i] = x - v + wpre;
    if (t == 1023) bsum[blockIdx.x] = wpre + x;
}

__global__ void k_scan_top(int* __restrict__ bsum, int nb) {
    __shared__ int warpsum[32];
    const int t = threadIdx.x, lane = t & 31, w = t >> 5;
    int v = (t < nb) ? bsum[t] : 0;
    int x = v;
#pragma unroll
    for (int off = 1; off < 32; off <<= 1) {
        int y = __shfl_up_sync(0xFFFFFFFFu, x, off);
        if (lane >= off) x += y;
    }
    if (lane == 31) warpsum[w] = x;
    __syncthreads();
    if (w == 0) {
        int s = warpsum[lane];
#pragma unroll
        for (int off = 1; off < 32; off <<= 1) {
            int y = __shfl_up_sync(0xFFFFFFFFu, s, off);
            if (lane >= off) s += y;
        }
        warpsum[lane] = s;
    }
    __syncthreads();
    int wpre = (w > 0) ? warpsum[w - 1] : 0;
    if (t < nb) bsum[t] = x - v + wpre;
    if (t == 1023) bsum[nb] = warpsum[31];
}

__global__ void k_scan_add(int* __restrict__ rowp, const int* __restrict__ bsum, int n, int nb) {
    int i = blockIdx.x * blockDim.x + threadIdx.x;
    if (i < n) rowp[i] += bsum[i >> 10];
    if (i == n) rowp[n] = bsum[nb];
}

__global__ void k_dinv_cursor(const int* __restrict__ cnt, const int* __restrict__ rowp,
                              float* __restrict__ dinv, int* __restrict__ cur, int n) {
    int i = blockIdx.x * blockDim.x + threadIdx.x;
    if (i >= n) return;
    dinv[i] = rsqrtf((float)cnt[i] + 1.0f);
    cur[i]  = rowp[i];
}

__global__ void k_scatter(const void* __restrict__ ei, long long E,
                          int* __restrict__ cur, int* __restrict__ colA) {
    long long i = (long long)blockIdx.x * blockDim.x + threadIdx.x;
    if (i >= E) return;
    int is64 = g_is64;
    int s = (int)edge_at(ei, i, is64);
    int d = (int)edge_at(ei, E + i, is64);
    int pos = atomicAdd(&cur[d], 1);
    colA[pos] = s;
}

// ---------------------------------------------------------------------------
// GEMM1: H16[M,512] = A16[M,512] @ Wt[512,512]^T  (raw fp16 out)
// Block 128x256, 512 threads (16 warps 4x4), warp tile 32x64, BK=32,
// 3-stage cp.async, ONE barrier per ktile. Dyn smem 72 KB.
// ---------------------------------------------------------------------------
#define G1_SMEM (3 * (8192 + 16384))

__global__ __launch_bounds__(512, 1)
void k_gemm_big(const __half* __restrict__ A, const __half* __restrict__ Bt,
                __half* __restrict__ H)
{
    extern __shared__ __align__(16) char smem[];
    const uint32_t sbA = smem_u32(smem);
    const uint32_t sbB = sbA + 3 * 8192;

    const int t   = threadIdx.x;
    const int L   = t & 31;
    const int wid = t >> 5;
    const int wm  = wid >> 2;
    const int wn  = wid & 3;
    const int g   = L >> 2;
    const int c   = L & 3;
    const int m0  = blockIdx.y * 128;
    const int n0  = blockIdx.x * 256;

    const uint32_t aLane = ((uint32_t)((L >> 4) & 1)) * 128u
                         + (uint32_t)(wm * 32) + (uint32_t)(L & 7) + ((uint32_t)((L >> 3) & 1)) * 8u;
    const uint32_t bLane = ((uint32_t)((L >> 3) & 1)) * 256u
                         + (uint32_t)(wn * 64) + (uint32_t)(L & 7) + ((uint32_t)((L >> 4) & 1)) * 8u;

    const int a_row = t & 127, a_k8 = t >> 7;
    const int b_r0  = t & 255, b_k0 = t >> 8;
    const int b_r1  = b_r0,    b_k1 = b_k0 + 2;

    float acc[2][8][4];
#pragma unroll
    for (int i = 0; i < 2; i++)
#pragma unroll
        for (int j = 0; j < 8; j++)
#pragma unroll
            for (int q = 0; q < 4; q++) acc[i][j][q] = 0.0f;

    auto issue = [&](int kt) {
        const int stg = kt % 3;
        const int k0 = kt * 32;
        cp_async16(sbA + stg * 8192u + (uint32_t)t * 16u,
                   A + (size_t)(m0 + a_row) * 512 + k0 + a_k8 * 8);
        uint32_t bbase = sbB + stg * 16384u;
        cp_async16(bbase + (uint32_t)t * 16u,
                   Bt + (size_t)(n0 + b_r0) * 512 + k0 + b_k0 * 8);
        cp_async16(bbase + (uint32_t)(t + 512) * 16u,
                   Bt + (size_t)(n0 + b_r1) * 512 + k0 + b_k1 * 8);
        CP_COMMIT();
    };

    issue(0);
    issue(1);

    for (int kt = 0; kt < 16; kt++) {
        if (kt + 1 < 16) { CP_WAIT1(); } else { CP_WAIT0(); }
        __syncthreads();

        const int stg = kt % 3;
        const uint32_t aB = sbA + stg * 8192u;
        const uint32_t bB = sbB + stg * 16384u;
#pragma unroll
        for (int kk = 0; kk < 2; kk++) {
            uint32_t af[2][4];
            uint32_t bf[8][2];
#pragma unroll
            for (int fm = 0; fm < 2; fm++)
                ldsm_x4(af[fm][0], af[fm][1], af[fm][2], af[fm][3],
                        aB + (aLane + (uint32_t)(kk * 256 + fm * 16)) * 16u);
#pragma unroll
            for (int p = 0; p < 4; p++)
                ldsm_x4(bf[2 * p][0], bf[2 * p][1], bf[2 * p + 1][0], bf[2 * p + 1][1],
                        bB + (bLane + (uint32_t)(kk * 512 + p * 16)) * 16u);
#pragma unroll
            for (int fm = 0; fm < 2; fm++)
#pragma unroll
                for (int fn = 0; fn < 8; fn++)
                    MMA16816(acc[fm][fn], af[fm], bf[fn]);
        }

        // Safe without a trailing barrier: stage (kt+2)%3 == (kt-1)%3 was fully
        // consumed before this iteration's top barrier.
        if (kt + 2 < 16) issue(kt + 2);
    }

    // epilogue: raw fp16 store (rows padded; no M guard needed)
#pragma unroll
    for (int fm = 0; fm < 2; fm++) {
        int r0 = m0 + wm * 32 + fm * 16 + g;
        int r1 = r0 + 8;
#pragma unroll
        for (int fn = 0; fn < 8; fn++) {
            int col = n0 + wn * 64 + fn * 8 + c * 2;
            __half2 v0 = __floats2half2_rn(acc[fm][fn][0], acc[fm][fn][1]);
            __half2 v1 = __floats2half2_rn(acc[fm][fn][2], acc[fm][fn][3]);
            *(__half2*)&H[(size_t)r0 * 512 + col] = v0;
            *(__half2*)&H[(size_t)r1 * 512 + col] = v1;
        }
    }
}

// ---------------------------------------------------------------------------
// GEMM2: Hs2h[M,128] = (A16[M,512] @ Wt2[128,512]^T) * dinv[row]  (fp16 out)
// Block 128x128, warp 32x64 (8 warps 4x2), BK=32, double-buffered.
// ---------------------------------------------------------------------------
__global__ __launch_bounds__(256, 2)
void k_gemm2(const __half* __restrict__ A, const __half* __restrict__ Bt,
             const float* __restrict__ dinv, __half* __restrict__ Hs, int M)
{
    __shared__ __align__(16) char smem[32768];
    const uint32_t sbA = smem_u32(smem);
    const uint32_t sbB = sbA + 16384;

    const int t   = threadIdx.x;
    const int L   = t & 31;
    const int wid = t >> 5;
    const int wm  = wid >> 1;
    const int wn  = wid & 1;
    const int g   = L >> 2;
    const int c   = L & 3;
    const int m0  = blockIdx.y * 128;

    const uint32_t aLane = ((uint32_t)((L >> 4) & 1)) * 128u
                         + (uint32_t)(wm * 32) + (uint32_t)(L & 7) + ((uint32_t)((L >> 3) & 1)) * 8u;
    const uint32_t bLane = ((uint32_t)((L >> 3) & 1)) * 128u
                         + (uint32_t)(wn * 64) + (uint32_t)(L & 7) + ((uint32_t)((L >> 4) & 1)) * 8u;

    const int s0 = t, s1 = t + 256;
    const int r0s = s0 & 127, k80 = s0 >> 7;
    const int r1s = s1 & 127, k81 = s1 >> 7;

    float acc[2][8][4];
#pragma unroll
    for (int i = 0; i < 2; i++)
#pragma unroll
        for (int j = 0; j < 8; j++)
#pragma unroll
            for (int q = 0; q < 4; q++) acc[i][j][q] = 0.0f;

    {
        cp_async16(sbA + s0 * 16u, A + (size_t)(m0 + r0s) * 512 + k80 * 8);
        cp_async16(sbA + s1 * 16u, A + (size_t)(m0 + r1s) * 512 + k81 * 8);
        cp_async16(sbB + s0 * 16u, Bt + (size_t)r0s * 512 + k80 * 8);
        cp_async16(sbB + s1 * 16u, Bt + (size_t)r1s * 512 + k81 * 8);
        CP_COMMIT();
        CP_WAIT0();
    }
    __syncthreads();

    for (int kt = 0; kt < 16; kt++) {
        const int buf  = kt & 1;
        const int nbuf = 1 - buf;
        const bool nxt = (kt + 1) < 16;

        if (nxt) {
            const int k0 = (kt + 1) * 32;
            cp_async16(sbA + nbuf * 8192u + s0 * 16u, A + (size_t)(m0 + r0s) * 512 + k0 + k80 * 8);
            cp_async16(sbA + nbuf * 8192u + s1 * 16u, A + (size_t)(m0 + r1s) * 512 + k0 + k81 * 8);
            cp_async16(sbB + nbuf * 8192u + s0 * 16u, Bt + (size_t)r0s * 512 + k0 + k80 * 8);
            cp_async16(sbB + nbuf * 8192u + s1 * 16u, Bt + (size_t)r1s * 512 + k0 + k81 * 8);
            CP_COMMIT();
        }

        const uint32_t aB = sbA + buf * 8192u;
        const uint32_t bB = sbB + buf * 8192u;
#pragma unroll
        for (int kk = 0; kk < 2; kk++) {
            uint32_t af[2][4];
            uint32_t bf[8][2];
#pragma unroll
            for (int fm = 0; fm < 2; fm++)
                ldsm_x4(af[fm][0], af[fm][1], af[fm][2], af[fm][3],
                        aB + (aLane + (uint32_t)(kk * 256 + fm * 16)) * 16u);
#pragma unroll
            for (int p = 0; p < 4; p++)
                ldsm_x4(bf[2 * p][0], bf[2 * p][1], bf[2 * p + 1][0], bf[2 * p + 1][1],
                        bB + (bLane + (uint32_t)(kk * 256 + p * 16)) * 16u);
#pragma unroll
            for (int fm = 0; fm < 2; fm++)
#pragma unroll
                for (int fn = 0; fn < 8; fn++)
                    MMA16816(acc[fm][fn], af[fm], bf[fn]);
        }

        if (nxt) CP_WAIT0();
        __syncthreads();
    }

#pragma unroll
    for (int fm = 0; fm < 2; fm++) {
        int r0 = m0 + wm * 32 + fm * 16 + g;
        int r1 = r0 + 8;
        float d0 = (r0 < M) ? dinv[r0] : 0.0f;
        float d1 = (r1 < M) ? dinv[r1] : 0.0f;
#pragma unroll
        for (int fn = 0; fn < 8; fn++) {
            int col = wn * 64 + fn * 8 + c * 2;
            if (r0 < M) {
                __half2 v = __floats2half2_rn(acc[fm][fn][0] * d0, acc[fm][fn][1] * d0);
                *(__half2*)&Hs[(size_t)r0 * 128 + col] = v;
            }
            if (r1 < M) {
                __half2 v = __floats2half2_rn(acc[fm][fn][2] * d1, acc[fm][fn][3] * d1);
                *(__half2*)&Hs[(size_t)r1 * 128 + col] = v;
            }
        }
    }
}

// ---------------------------------------------------------------------------
// pull1 (fp16, 2-way unrolled): agg16 = h16(b1 + dinv_d*(h[d]*dinv_d + sum h[s]*dinv_s))
// ---------------------------------------------------------------------------
__global__ void k_pull1_h(const int* __restrict__ rowp, const int* __restrict__ colA,
                          const __half* __restrict__ h16, const float* __restrict__ dinv,
                          const float* __restrict__ bias, __half* __restrict__ agg16,
                          int n, int cbase) {
    int idx = blockIdx.x * blockDim.x + threadIdx.x;
    int dst = idx >> 5;
    int j   = idx & 31;
    if (dst >= n) return;
    const uint2* h2p = (const uint2*)h16;
    const int u = cbase + j;

    float dd = __ldg(&dinv[dst]);
    uint2 sv = h2p[(size_t)dst * 128 + u];
    float2 f0 = __half22float2(*(__half2*)&sv.x), f1 = __half22float2(*(__half2*)&sv.y);
    float4 acc = make_float4(f0.x * dd, f0.y * dd, f1.x * dd, f1.y * dd);

    int e0 = __ldg(&rowp[dst]);
    int e1 = __ldg(&rowp[dst + 1]);
    int e  = e0;
    for (; e + 2 <= e1; e += 2) {
        int sA = __ldg(&colA[e]);
        int sB = __ldg(&colA[e + 1]);
        float dA = __ldg(&dinv[sA]);
        float dB = __ldg(&dinv[sB]);
        uint2 vA = h2p[(size_t)sA * 128 + u];
        uint2 vB = h2p[(size_t)sB * 128 + u];
        float2 a0 = __half22float2(*(__half2*)&vA.x), a1 = __half22float2(*(__half2*)&vA.y);
        float2 b0 = __half22float2(*(__half2*)&vB.x), b1 = __half22float2(*(__half2*)&vB.y);
        acc.x += a0.x * dA + b0.x * dB;
        acc.y += a0.y * dA + b0.y * dB;
        acc.z += a1.x * dA + b1.x * dB;
        acc.w += a1.y * dA + b1.y * dB;
    }
    if (e < e1) {
        int s = __ldg(&colA[e]);
        float ds = __ldg(&dinv[s]);
        uint2 hv = h2p[(size_t)s * 128 + u];
        float2 g0 = __half22float2(*(__half2*)&hv.x), g1 = __half22float2(*(__half2*)&hv.y);
        acc.x += g0.x * ds; acc.y += g0.y * ds;
        acc.z += g1.x * ds; acc.w += g1.y * ds;
    }

    float4 bb = ((const float4*)bias)[u];
    __half2 o0 = __floats2half2_rn(bb.x + acc.x * dd, bb.y + acc.y * dd);
    __half2 o1 = __floats2half2_rn(bb.z + acc.z * dd, bb.w + acc.w * dd);
    uint2 ov = make_uint2(*(uint32_t*)&o0, *(uint32_t*)&o1);
    __stcs((uint2*)&((uint2*)agg16)[(size_t)dst * 128 + u], ov);
}

// ---------------------------------------------------------------------------
// pull2 (fp16 gather, fp32 out, 2-way unrolled): out = b2 + dinv_d*(hs[d] + sum hs[s])
// ---------------------------------------------------------------------------
__global__ void k_pull2(const int* __restrict__ rowp, const int* __restrict__ colA,
                        const __half* __restrict__ hs, const float* __restrict__ dinv,
                        const float* __restrict__ bias, float* __restrict__ out, int n) {
    int idx = blockIdx.x * blockDim.x + threadIdx.x;
    int dst = idx >> 5;
    int j   = idx & 31;
    if (dst >= n) return;
    const uint2* h2p = (const uint2*)hs;   // 32 uint2 per 128-feat row

    uint2 sv = h2p[(size_t)dst * 32 + j];
    float2 f0 = __half22float2(*(__half2*)&sv.x), f1 = __half22float2(*(__half2*)&sv.y);
    float4 acc = make_float4(f0.x, f0.y, f1.x, f1.y);

    int e0 = __ldg(&rowp[dst]);
    int e1 = __ldg(&rowp[dst + 1]);
    int e  = e0;
    for (; e + 2 <= e1; e += 2) {
        int sA = __ldg(&colA[e]);
        int sB = __ldg(&colA[e + 1]);
        uint2 vA = h2p[(size_t)sA * 32 + j];
        uint2 vB = h2p[(size_t)sB * 32 + j];
        float2 a0 = __half22float2(*(__half2*)&vA.x), a1 = __half22float2(*(__half2*)&vA.y);
        float2 b0 = __half22float2(*(__half2*)&vB.x), b1 = __half22float2(*(__half2*)&vB.y);
        acc.x += a0.x + b0.x; acc.y += a0.y + b0.y;
        acc.z += a1.x + b1.x; acc.w += a1.y + b1.y;
    }
    if (e < e1) {
        int s = __ldg(&colA[e]);
        uint2 hv = h2p[(size_t)s * 32 + j];
        float2 g0 = __half22float2(*(__half2*)&hv.x), g1 = __half22float2(*(__half2*)&hv.y);
        acc.x += g0.x; acc.y += g0.y; acc.z += g1.x; acc.w += g1.y;
    }

    float d = dinv[dst];
    float4 bb = ((const float4*)bias)[j];
    float4 o = make_float4(bb.x + acc.x * d, bb.y + acc.y * d,
                           bb.z + acc.z * d, bb.w + acc.w * d);
    __stcs(&((float4*)out)[(size_t)dst * 32 + j], o);
}

// ---------------------------------------------------------------------------
extern "C" void kernel_launch(void* const* d_in, const int* in_sizes, int n_in,
                              void* d_out, int out_size) {
    const float* x   = (const float*)d_in[0];
    const void*  ei  = d_in[1];
    const float* W1  = (const float*)d_in[3];
    const float* b1  = (const float*)d_in[4];
    const float* W2  = (const float*)d_in[5];
    const float* b2  = (const float*)d_in[6];
    float*       out = (float*)d_out;

    const long long nelem = (long long)in_sizes[1];
    const long long E     = nelem / 2;
    const int dhid        = in_sizes[4];         // 512
    const int dout        = in_sizes[6];         // 128
    const int din         = in_sizes[3] / dhid;  // 512
    const int n           = in_sizes[0] / din;   // 100000

    __half *xh_p, *h16_p, *agg16_p, *wt1_p, *wt2_p, *hs2h_p;
    float *dinv_p;
    int *cnt_p, *rowp_p, *cur_p, *col_p, *bsum_p;
    cudaGetSymbolAddress((void**)&xh_p,    g_xh);
    cudaGetSymbolAddress((void**)&h16_p,   g_h16);
    cudaGetSymbolAddress((void**)&agg16_p, g_agg16);
    cudaGetSymbolAddress((void**)&wt1_p,   g_wt1);
    cudaGetSymbolAddress((void**)&wt2_p,   g_wt2);
    cudaGetSymbolAddress((void**)&hs2h_p,  g_hs2h);
    cudaGetSymbolAddress((void**)&dinv_p,  g_dinv);
    cudaGetSymbolAddress((void**)&cnt_p,   g_cnt);
    cudaGetSymbolAddress((void**)&rowp_p,  g_rowp);
    cudaGetSymbolAddress((void**)&cur_p,   g_cur);
    cudaGetSymbolAddress((void**)&col_p,   g_col);
    cudaGetSymbolAddress((void**)&bsum_p,  g_bsum);

    static bool attr_set = false;
    if (!attr_set) {
        cudaFuncSetAttribute(k_gemm_big, cudaFuncAttributeMaxDynamicSharedMemorySize, G1_SMEM);
        attr_set = true;
    }

    const int eb   = (int)((E + 255) / 256);
    const int nb   = (n + 255) / 256;
    const int nblk = (n + 1023) / 1024;
    const int pull_blocks = (int)(((long long)n * 32 + 255) / 256);

    // 1: x->fp16 + zero cnt + detect
    k_xcvt_init<<<(MAXN * 64 + 255) / 256, 256>>>(x, ei, nelem, n, xh_p, cnt_p);
    // 2: W1^T fp16
    {
        dim3 grid(dhid / 32, din / 32), blk(32, 8);
        k_transpose_h<<<grid, blk>>>(W1, wt1_p, din, dhid);
    }
    // 3: degree histogram
    k_hist<<<eb, 256>>>(ei, E, cnt_p);
    // 4: GEMM1 -- profiled slot
    {
        dim3 grid(2, (n + 127) / 128);
        k_gemm_big<<<grid, 512, G1_SMEM>>>(xh_p, wt1_p, h16_p);
    }
    // 5: W2^T fp16
    {
        dim3 grid(dout / 32, dhid / 32), blk(32, 8);
        k_transpose_h<<<grid, blk>>>(W2, wt2_p, dhid, dout);
    }
    // 6-10: CSR build + dinv
    k_scan_blk<<<nblk, 1024>>>(cnt_p, rowp_p, bsum_p, n);
    k_scan_top<<<1, 1024>>>(bsum_p, nblk);
    k_scan_add<<<(n + 256) / 256, 256>>>(rowp_p, bsum_p, n, nblk);
    k_dinv_cursor<<<nb, 256>>>(cnt_p, rowp_p, dinv_p, cur_p, n);
    k_scatter<<<eb, 256>>>(ei, E, cur_p, col_p);

    // 11-14: layer-1 pull, 4 chunks of 128 feats
    for (int cidx = 0; cidx < 4; cidx++) {
        k_pull1_h<<<pull_blocks, 256>>>(rowp_p, col_p, h16_p, dinv_p,
                                        b1, agg16_p, n, cidx * 32);
    }

    // 15: GEMM2 (fp16 out)
    {
        dim3 grid(1, (n + 127) / 128);
        k_gemm2<<<grid, 256>>>(agg16_p, wt2_p, dinv_p, hs2h_p, n);
    }
    // 16: layer-2 pull
    k_pull2<<<pull_blocks, 256>>>(rowp_p, col_p, hs2h_p, dinv_p, b2, out, n);

    (void)n_in; (void)out_size;
}

// round 12
// speedup vs baseline: 1.4211x; 1.0521x over previous
#include <cuda_runtime.h>
#include <cuda_fp16.h>
#include <stdint.h>

// ---------------------------------------------------------------------------
// GCN 2-layer, fp16 tensor-core GEMMs (m16n8k16, fp32 accum), fp16 feature
// buffers, CSR pull aggregation. Two-stream overlap:
//   stream0: xcvt -> W1^T -> GEMM1 -> (join) -> pull1 x4 -> GEMM2 -> pull2
//   streamB: init/detect -> hist -> scan -> dinv/cursor -> scatter -> W2^T
// ---------------------------------------------------------------------------

#define MAXN 100352
#define MAXE 1048576

__device__ __half g_xh[(size_t)MAXN * 512];
__device__ __half g_h16[(size_t)MAXN * 512];
__device__ __half g_agg16[(size_t)MAXN * 512];
__device__ __half g_hs2h[(size_t)MAXN * 128];
__device__ __half g_wt1[(size_t)512 * 512];
__device__ __half g_wt2[(size_t)128 * 512];
__device__ float  g_dinv[MAXN];
__device__ int    g_cnt[MAXN];
__device__ int    g_rowp[MAXN + 1];
__device__ int    g_cur[MAXN];
__device__ int    g_col[MAXE];
__device__ int    g_bsum[1025];
__device__ int    g_is64;

// --------- side stream + events, created pre-main (global ctor) ------------
struct StreamHolder {
    cudaStream_t s;
    cudaEvent_t  e0, e1;
    bool ok;
    StreamHolder() {
        ok = (cudaStreamCreateWithFlags(&s, cudaStreamNonBlocking) == cudaSuccess);
        ok = ok && (cudaEventCreateWithFlags(&e0, cudaEventDisableTiming) == cudaSuccess);
        ok = ok && (cudaEventCreateWithFlags(&e1, cudaEventDisableTiming) == cudaSuccess);
        if (!ok) s = 0;
    }
};
static StreamHolder g_sh;

// ------------------------------- helpers -----------------------------------
__device__ __forceinline__ uint32_t smem_u32(const void* p) {
    uint32_t a;
    asm("{ .reg .u64 t; cvta.to.shared.u64 t, %1; cvt.u32.u64 %0, t; }" : "=r"(a) : "l"(p));
    return a;
}
__device__ __forceinline__ void ldsm_x4(uint32_t& r0, uint32_t& r1, uint32_t& r2, uint32_t& r3,
                                        uint32_t addr) {
    asm volatile("ldmatrix.sync.aligned.m8n8.x4.shared.b16 {%0,%1,%2,%3}, [%4];"
                 : "=r"(r0), "=r"(r1), "=r"(r2), "=r"(r3) : "r"(addr));
}
__device__ __forceinline__ void cp_async16(uint32_t dst, const void* src) {
    asm volatile("cp.async.ca.shared.global [%0], [%1], 16;" :: "r"(dst), "l"(src) : "memory");
}
#define CP_COMMIT() asm volatile("cp.async.commit_group;" ::: "memory")
#define CP_WAIT0()  asm volatile("cp.async.wait_group 0;" ::: "memory")
#define CP_WAIT1()  asm volatile("cp.async.wait_group 1;" ::: "memory")

#define MMA16816(acc, af, bf)                                                  \
    asm volatile(                                                              \
        "mma.sync.aligned.m16n8k16.row.col.f32.f16.f16.f32 "                   \
        "{%0,%1,%2,%3}, {%4,%5,%6,%7}, {%8,%9}, {%0,%1,%2,%3};"                \
        : "+f"((acc)[0]), "+f"((acc)[1]), "+f"((acc)[2]), "+f"((acc)[3])       \
        : "r"((af)[0]), "r"((af)[1]), "r"((af)[2]), "r"((af)[3]),              \
          "r"((bf)[0]), "r"((bf)[1]))

__device__ __forceinline__ long long edge_at(const void* ei, long long idx, int is64) {
    if (is64) return ((const long long*)ei)[idx];
    return (long long)((const int*)ei)[idx];
}

// ---------------------------------------------------------------------------
// stream0: x -> fp16 (zero-pad rows >= n)
// ---------------------------------------------------------------------------
__global__ void k_xcvt(const float* __restrict__ x, int n, __half* __restrict__ xh) {
    int gid = blockIdx.x * blockDim.x + threadIdx.x;
    const int total = MAXN * 64;
    if (gid >= total) return;
    int row = gid >> 6, u = gid & 63;
    uint4 o;
    if (row < n) {
        const float4 v0 = *(const float4*)&x[(size_t)row * 512 + u * 8];
        const float4 v1 = *(const float4*)&x[(size_t)row * 512 + u * 8 + 4];
        __half2 h0 = __floats2half2_rn(v0.x, v0.y);
        __half2 h1 = __floats2half2_rn(v0.z, v0.w);
        __half2 h2 = __floats2half2_rn(v1.x, v1.y);
        __half2 h3 = __floats2half2_rn(v1.z, v1.w);
        o = make_uint4(*(uint32_t*)&h0, *(uint32_t*)&h1, *(uint32_t*)&h2, *(uint32_t*)&h3);
    } else {
        o = make_uint4(0, 0, 0, 0);
    }
    *(uint4*)&xh[(size_t)gid * 8] = o;
}

// streamB: zero cnt + dtype detect
__global__ void k_init(const void* ei, long long nelem, int n, int* cnt) {
    int i = blockIdx.x * blockDim.x + threadIdx.x;
    if (i < n) cnt[i] = 0;
    if (blockIdx.x == 0 && threadIdx.x == 0) {
        const long long* p = (const long long*)ei;
        long long m = 64;
        if (m > nelem / 2) m = nelem / 2;
        int is64 = 1;
        for (long long j = 0; j < m; j++) {
            long long v = p[j];
            if (v < 0 || v >= (long long)n) { is64 = 0; break; }
        }
        g_is64 = is64;
    }
}

__global__ void k_transpose_h(const float* __restrict__ W, __half* __restrict__ Wt, int K, int N) {
    __shared__ float tile[32][33];
    int k0 = blockIdx.y * 32, n0 = blockIdx.x * 32;
    int tx = threadIdx.x, ty = threadIdx.y;  // 32 x 8
    for (int j = 0; j < 32; j += 8)
        tile[ty + j][tx] = W[(size_t)(k0 + ty + j) * N + n0 + tx];
    __syncthreads();
    for (int j = 0; j < 32; j += 8)
        Wt[(size_t)(n0 + ty + j) * K + k0 + tx] = __float2half_rn(tile[tx][ty + j]);
}

__global__ void k_hist(const void* __restrict__ ei, long long E, int* __restrict__ cnt) {
    long long i = (long long)blockIdx.x * blockDim.x + threadIdx.x;
    if (i >= E) return;
    int d = (int)edge_at(ei, E + i, g_is64);
    atomicAdd(&cnt[d], 1);
}

__global__ void k_scan_blk(const int* __restrict__ cnt, int* __restrict__ rowp,
                           int* __restrict__ bsum, int n) {
    __shared__ int warpsum[32];
    const int t = threadIdx.x, lane = t & 31, w = t >> 5;
    int i = blockIdx.x * 1024 + t;
    int v = (i < n) ? cnt[i] : 0;
    int x = v;
#pragma unroll
    for (int off = 1; off < 32; off <<= 1) {
        int y = __shfl_up_sync(0xFFFFFFFFu, x, off);
        if (lane >= off) x += y;
    }
    if (lane == 31) warpsum[w] = x;
    __syncthreads();
    if (w == 0) {
        int s = warpsum[lane];
#pragma unroll
        for (int off = 1; off < 32; off <<= 1) {
            int y = __shfl_up_sync(0xFFFFFFFFu, s, off);
            if (lane >= off) s += y;
        }
        warpsum[lane] = s;
    }
    __syncthreads();
    int wpre = (w > 0) ? warpsum[w - 1] : 0;
    if (i < n) rowp[i] = x - v + wpre;
    if (t == 1023) bsum[blockIdx.x] = wpre + x;
}

__global__ void k_scan_top(int* __restrict__ bsum, int nb) {
    __shared__ int warpsum[32];
    const int t = threadIdx.x, lane = t & 31, w = t >> 5;
    int v = (t < nb) ? bsum[t] : 0;
    int x = v;
#pragma unroll
    for (int off = 1; off < 32; off <<= 1) {
        int y = __shfl_up_sync(0xFFFFFFFFu, x, off);
        if (lane >= off) x += y;
    }
    if (lane == 31) warpsum[w] = x;
    __syncthreads();
    if (w == 0) {
        int s = warpsum[lane];
#pragma unroll
        for (int off = 1; off < 32; off <<= 1) {
            int y = __shfl_up_sync(0xFFFFFFFFu, s, off);
            if (lane >= off) s += y;
        }
        warpsum[lane] = s;
    }
    __syncthreads();
    int wpre = (w > 0) ? warpsum[w - 1] : 0;
    if (t < nb) bsum[t] = x - v + wpre;
    if (t == 1023) bsum[nb] = warpsum[31];
}

__global__ void k_scan_add(int* __restrict__ rowp, const int* __restrict__ bsum, int n, int nb) {
    int i = blockIdx.x * blockDim.x + threadIdx.x;
    if (i < n) rowp[i] += bsum[i >> 10];
    if (i == n) rowp[n] = bsum[nb];
}

__global__ void k_dinv_cursor(const int* __restrict__ cnt, const int* __restrict__ rowp,
                              float* __restrict__ dinv, int* __restrict__ cur, int n) {
    int i = blockIdx.x * blockDim.x + threadIdx.x;
    if (i >= n) return;
    dinv[i] = rsqrtf((float)cnt[i] + 1.0f);
    cur[i]  = rowp[i];
}

__global__ void k_scatter(const void* __restrict__ ei, long long E,
                          int* __restrict__ cur, int* __restrict__ colA) {
    long long i = (long long)blockIdx.x * blockDim.x + threadIdx.x;
    if (i >= E) return;
    int is64 = g_is64;
    int s = (int)edge_at(ei, i, is64);
    int d = (int)edge_at(ei, E + i, is64);
    int pos = atomicAdd(&cur[d], 1);
    colA[pos] = s;
}

// ---------------------------------------------------------------------------
// GEMM1: H16[M,512] = A16[M,512] @ Wt[512,512]^T  (raw fp16 out)
// Block 128x256, 512 threads (16 warps 4x4), warp tile 32x64, BK=32,
// 3-stage cp.async. Dyn smem 72 KB.
// ---------------------------------------------------------------------------
#define G1_SMEM (3 * (8192 + 16384))

__global__ __launch_bounds__(512, 1)
void k_gemm_big(const __half* __restrict__ A, const __half* __restrict__ Bt,
                __half* __restrict__ H)
{
    extern __shared__ __align__(16) char smem[];
    const uint32_t sbA = smem_u32(smem);
    const uint32_t sbB = sbA + 3 * 8192;

    const int t   = threadIdx.x;
    const int L   = t & 31;
    const int wid = t >> 5;
    const int wm  = wid >> 2;
    const int wn  = wid & 3;
    const int g   = L >> 2;
    const int c   = L & 3;
    const int m0  = blockIdx.y * 128;
    const int n0  = blockIdx.x * 256;

    const uint32_t aLane = ((uint32_t)((L >> 4) & 1)) * 128u
                         + (uint32_t)(wm * 32) + (uint32_t)(L & 7) + ((uint32_t)((L >> 3) & 1)) * 8u;
    const uint32_t bLane = ((uint32_t)((L >> 3) & 1)) * 256u
                         + (uint32_t)(wn * 64) + (uint32_t)(L & 7) + ((uint32_t)((L >> 4) & 1)) * 8u;

    const int a_row = t & 127, a_k8 = t >> 7;
    const int b_r0  = t & 255, b_k0 = t >> 8;
    const int b_r1  = b_r0,    b_k1 = b_k0 + 2;

    float acc[2][8][4];
#pragma unroll
    for (int i = 0; i < 2; i++)
#pragma unroll
        for (int j = 0; j < 8; j++)
#pragma unroll
            for (int q = 0; q < 4; q++) acc[i][j][q] = 0.0f;

    auto issue = [&](int kt) {
        const int stg = kt % 3;
        const int k0 = kt * 32;
        cp_async16(sbA + stg * 8192u + (uint32_t)t * 16u,
                   A + (size_t)(m0 + a_row) * 512 + k0 + a_k8 * 8);
        uint32_t bbase = sbB + stg * 16384u;
        cp_async16(bbase + (uint32_t)t * 16u,
                   Bt + (size_t)(n0 + b_r0) * 512 + k0 + b_k0 * 8);
        cp_async16(bbase + (uint32_t)(t + 512) * 16u,
                   Bt + (size_t)(n0 + b_r1) * 512 + k0 + b_k1 * 8);
        CP_COMMIT();
    };

    issue(0);
    issue(1);

    for (int kt = 0; kt < 16; kt++) {
        if (kt + 1 < 16) { CP_WAIT1(); } else { CP_WAIT0(); }
        __syncthreads();

        const int stg = kt % 3;
        const uint32_t aB = sbA + stg * 8192u;
        const uint32_t bB = sbB + stg * 16384u;
#pragma unroll
        for (int kk = 0; kk < 2; kk++) {
            uint32_t af[2][4];
            uint32_t bf[8][2];
#pragma unroll
            for (int fm = 0; fm < 2; fm++)
                ldsm_x4(af[fm][0], af[fm][1], af[fm][2], af[fm][3],
                        aB + (aLane + (uint32_t)(kk * 256 + fm * 16)) * 16u);
#pragma unroll
            for (int p = 0; p < 4; p++)
                ldsm_x4(bf[2 * p][0], bf[2 * p][1], bf[2 * p + 1][0], bf[2 * p + 1][1],
                        bB + (bLane + (uint32_t)(kk * 512 + p * 16)) * 16u);
#pragma unroll
            for (int fm = 0; fm < 2; fm++)
#pragma unroll
                for (int fn = 0; fn < 8; fn++)
                    MMA16816(acc[fm][fn], af[fm], bf[fn]);
        }

        if (kt + 2 < 16) issue(kt + 2);
    }

#pragma unroll
    for (int fm = 0; fm < 2; fm++) {
        int r0 = m0 + wm * 32 + fm * 16 + g;
        int r1 = r0 + 8;
#pragma unroll
        for (int fn = 0; fn < 8; fn++) {
            int col = n0 + wn * 64 + fn * 8 + c * 2;
            __half2 v0 = __floats2half2_rn(acc[fm][fn][0], acc[fm][fn][1]);
            __half2 v1 = __floats2half2_rn(acc[fm][fn][2], acc[fm][fn][3]);
            *(__half2*)&H[(size_t)r0 * 512 + col] = v0;
            *(__half2*)&H[(size_t)r1 * 512 + col] = v1;
        }
    }
}

// ---------------------------------------------------------------------------
// GEMM2: Hs2h[M,128] = (A16[M,512] @ Wt2[128,512]^T) * dinv[row]  (fp16 out)
// ---------------------------------------------------------------------------
__global__ __launch_bounds__(256, 2)
void k_gemm2(const __half* __restrict__ A, const __half* __restrict__ Bt,
             const float* __restrict__ dinv, __half* __restrict__ Hs, int M)
{
    __shared__ __align__(16) char smem[32768];
    const uint32_t sbA = smem_u32(smem);
    const uint32_t sbB = sbA + 16384;

    const int t   = threadIdx.x;
    const int L   = t & 31;
    const int wid = t >> 5;
    const int wm  = wid >> 1;
    const int wn  = wid & 1;
    const int g   = L >> 2;
    const int c   = L & 3;
    const int m0  = blockIdx.y * 128;

    const uint32_t aLane = ((uint32_t)((L >> 4) & 1)) * 128u
                         + (uint32_t)(wm * 32) + (uint32_t)(L & 7) + ((uint32_t)((L >> 3) & 1)) * 8u;
    const uint32_t bLane = ((uint32_t)((L >> 3) & 1)) * 128u
                         + (uint32_t)(wn * 64) + (uint32_t)(L & 7) + ((uint32_t)((L >> 4) & 1)) * 8u;

    const int s0 = t, s1 = t + 256;
    const int r0s = s0 & 127, k80 = s0 >> 7;
    const int r1s = s1 & 127, k81 = s1 >> 7;

    float acc[2][8][4];
#pragma unroll
    for (int i = 0; i < 2; i++)
#pragma unroll
        for (int j = 0; j < 8; j++)
#pragma unroll
            for (int q = 0; q < 4; q++) acc[i][j][q] = 0.0f;

    {
        cp_async16(sbA + s0 * 16u, A + (size_t)(m0 + r0s) * 512 + k80 * 8);
        cp_async16(sbA + s1 * 16u, A + (size_t)(m0 + r1s) * 512 + k81 * 8);
        cp_async16(sbB + s0 * 16u, Bt + (size_t)r0s * 512 + k80 * 8);
        cp_async16(sbB + s1 * 16u, Bt + (size_t)r1s * 512 + k81 * 8);
        CP_COMMIT();
        CP_WAIT0();
    }
    __syncthreads();

    for (int kt = 0; kt < 16; kt++) {
        const int buf  = kt & 1;
        const int nbuf = 1 - buf;
        const bool nxt = (kt + 1) < 16;

        if (nxt) {
            const int k0 = (kt + 1) * 32;
            cp_async16(sbA + nbuf * 8192u + s0 * 16u, A + (size_t)(m0 + r0s) * 512 + k0 + k80 * 8);
            cp_async16(sbA + nbuf * 8192u + s1 * 16u, A + (size_t)(m0 + r1s) * 512 + k0 + k81 * 8);
            cp_async16(sbB + nbuf * 8192u + s0 * 16u, Bt + (size_t)r0s * 512 + k0 + k80 * 8);
            cp_async16(sbB + nbuf * 8192u + s1 * 16u, Bt + (size_t)r1s * 512 + k0 + k81 * 8);
            CP_COMMIT();
        }

        const uint32_t aB = sbA + buf * 8192u;
        const uint32_t bB = sbB + buf * 8192u;
#pragma unroll
        for (int kk = 0; kk < 2; kk++) {
            uint32_t af[2][4];
            uint32_t bf[8][2];
#pragma unroll
            for (int fm = 0; fm < 2; fm++)
                ldsm_x4(af[fm][0], af[fm][1], af[fm][2], af[fm][3],
                        aB + (aLane + (uint32_t)(kk * 256 + fm * 16)) * 16u);
#pragma unroll
            for (int p = 0; p < 4; p++)
                ldsm_x4(bf[2 * p][0], bf[2 * p][1], bf[2 * p + 1][0], bf[2 * p + 1][1],
                        bB + (bLane + (uint32_t)(kk * 256 + p * 16)) * 16u);
#pragma unroll
            for (int fm = 0; fm < 2; fm++)
#pragma unroll
                for (int fn = 0; fn < 8; fn++)
                    MMA16816(acc[fm][fn], af[fm], bf[fn]);
        }

        if (nxt) CP_WAIT0();
        __syncthreads();
    }

#pragma unroll
    for (int fm = 0; fm < 2; fm++) {
        int r0 = m0 + wm * 32 + fm * 16 + g;
        int r1 = r0 + 8;
        float d0 = (r0 < M) ? dinv[r0] : 0.0f;
        float d1 = (r1 < M) ? dinv[r1] : 0.0f;
#pragma unroll
        for (int fn = 0; fn < 8; fn++) {
            int col = wn * 64 + fn * 8 + c * 2;
            if (r0 < M) {
                __half2 v = __floats2half2_rn(acc[fm][fn][0] * d0, acc[fm][fn][1] * d0);
                *(__half2*)&Hs[(size_t)r0 * 128 + col] = v;
            }
            if (r1 < M) {
                __half2 v = __floats2half2_rn(acc[fm][fn][2] * d1, acc[fm][fn][3] * d1);
                *(__half2*)&Hs[(size_t)r1 * 128 + col] = v;
            }
        }
    }
}

// ---------------------------------------------------------------------------
// pull1 (fp16, 4-way unrolled)
// ---------------------------------------------------------------------------
__global__ void k_pull1_h(const int* __restrict__ rowp, const int* __restrict__ colA,
                          const __half* __restrict__ h16, const float* __restrict__ dinv,
                          const float* __restrict__ bias, __half* __restrict__ agg16,
                          int n, int cbase) {
    int idx = blockIdx.x * blockDim.x + threadIdx.x;
    int dst = idx >> 5;
    int j   = idx & 31;
    if (dst >= n) return;
    const uint2* h2p = (const uint2*)h16;
    const int u = cbase + j;

    float dd = __ldg(&dinv[dst]);
    uint2 sv = h2p[(size_t)dst * 128 + u];
    float2 f0 = __half22float2(*(__half2*)&sv.x), f1 = __half22float2(*(__half2*)&sv.y);
    float4 acc = make_float4(f0.x * dd, f0.y * dd, f1.x * dd, f1.y * dd);

    int e0 = __ldg(&rowp[dst]);
    int e1 = __ldg(&rowp[dst + 1]);
    int e  = e0;
    for (; e + 4 <= e1; e += 4) {
        int s0 = __ldg(&colA[e]);
        int s1 = __ldg(&colA[e + 1]);
        int s2 = __ldg(&colA[e + 2]);
        int s3 = __ldg(&colA[e + 3]);
        float d0 = __ldg(&dinv[s0]);
        float d1 = __ldg(&dinv[s1]);
        float d2 = __ldg(&dinv[s2]);
        float d3 = __ldg(&dinv[s3]);
        uint2 v0 = h2p[(size_t)s0 * 128 + u];
        uint2 v1 = h2p[(size_t)s1 * 128 + u];
        uint2 v2 = h2p[(size_t)s2 * 128 + u];
        uint2 v3 = h2p[(size_t)s3 * 128 + u];
        float2 a0 = __half22float2(*(__half2*)&v0.x), a1 = __half22float2(*(__half2*)&v0.y);
        float2 b0 = __half22float2(*(__half2*)&v1.x), b1 = __half22float2(*(__half2*)&v1.y);
        float2 c0 = __half22float2(*(__half2*)&v2.x), c1 = __half22float2(*(__half2*)&v2.y);
        float2 q0 = __half22float2(*(__half2*)&v3.x), q1 = __half22float2(*(__half2*)&v3.y);
        acc.x += a0.x * d0 + b0.x * d1 + c0.x * d2 + q0.x * d3;
        acc.y += a0.y * d0 + b0.y * d1 + c0.y * d2 + q0.y * d3;
        acc.z += a1.x * d0 + b1.x * d1 + c1.x * d2 + q1.x * d3;
        acc.w += a1.y * d0 + b1.y * d1 + c1.y * d2 + q1.y * d3;
    }
    for (; e < e1; e++) {
        int s = __ldg(&colA[e]);
        float ds = __ldg(&dinv[s]);
        uint2 hv = h2p[(size_t)s * 128 + u];
        float2 g0 = __half22float2(*(__half2*)&hv.x), g1 = __half22float2(*(__half2*)&hv.y);
        acc.x += g0.x * ds; acc.y += g0.y * ds;
        acc.z += g1.x * ds; acc.w += g1.y * ds;
    }

    float4 bb = ((const float4*)bias)[u];
    __half2 o0 = __floats2half2_rn(bb.x + acc.x * dd, bb.y + acc.y * dd);
    __half2 o1 = __floats2half2_rn(bb.z + acc.z * dd, bb.w + acc.w * dd);
    uint2 ov = make_uint2(*(uint32_t*)&o0, *(uint32_t*)&o1);
    __stcs((uint2*)&((uint2*)agg16)[(size_t)dst * 128 + u], ov);
}

// ---------------------------------------------------------------------------
// pull2 (fp16 gather, fp32 out, 4-way unrolled)
// ---------------------------------------------------------------------------
__global__ void k_pull2(const int* __restrict__ rowp, const int* __restrict__ colA,
                        const __half* __restrict__ hs, const float* __restrict__ dinv,
                        const float* __restrict__ bias, float* __restrict__ out, int n) {
    int idx = blockIdx.x * blockDim.x + threadIdx.x;
    int dst = idx >> 5;
    int j   = idx & 31;
    if (dst >= n) return;
    const uint2* h2p = (const uint2*)hs;

    uint2 sv = h2p[(size_t)dst * 32 + j];
    float2 f0 = __half22float2(*(__half2*)&sv.x), f1 = __half22float2(*(__half2*)&sv.y);
    float4 acc = make_float4(f0.x, f0.y, f1.x, f1.y);

    int e0 = __ldg(&rowp[dst]);
    int e1 = __ldg(&rowp[dst + 1]);
    int e  = e0;
    for (; e + 4 <= e1; e += 4) {
        int s0 = __ldg(&colA[e]);
        int s1 = __ldg(&colA[e + 1]);
        int s2 = __ldg(&colA[e + 2]);
        int s3 = __ldg(&colA[e + 3]);
        uint2 v0 = h2p[(size_t)s0 * 32 + j];
        uint2 v1 = h2p[(size_t)s1 * 32 + j];
        uint2 v2 = h2p[(size_t)s2 * 32 + j];
        uint2 v3 = h2p[(size_t)s3 * 32 + j];
        float2 a0 = __half22float2(*(__half2*)&v0.x), a1 = __half22float2(*(__half2*)&v0.y);
        float2 b0 = __half22float2(*(__half2*)&v1.x), b1 = __half22float2(*(__half2*)&v1.y);
        float2 c0 = __half22float2(*(__half2*)&v2.x), c1 = __half22float2(*(__half2*)&v2.y);
        float2 q0 = __half22float2(*(__half2*)&v3.x), q1 = __half22float2(*(__half2*)&v3.y);
        acc.x += a0.x + b0.x + c0.x + q0.x;
        acc.y += a0.y + b0.y + c0.y + q0.y;
        acc.z += a1.x + b1.x + c1.x + q1.x;
        acc.w += a1.y + b1.y + c1.y + q1.y;
    }
    for (; e < e1; e++) {
        int s = __ldg(&colA[e]);
        uint2 hv = h2p[(size_t)s * 32 + j];
        float2 g0 = __half22float2(*(__half2*)&hv.x), g1 = __half22float2(*(__half2*)&hv.y);
        acc.x += g0.x; acc.y += g0.y; acc.z += g1.x; acc.w += g1.y;
    }

    float d = dinv[dst];
    float4 bb = ((const float4*)bias)[j];
    float4 o = make_float4(bb.x + acc.x * d, bb.y + acc.y * d,
                           bb.z + acc.z * d, bb.w + acc.w * d);
    __stcs(&((float4*)out)[(size_t)dst * 32 + j], o);
}

// ---------------------------------------------------------------------------
extern "C" void kernel_launch(void* const* d_in, const int* in_sizes, int n_in,
                              void* d_out, int out_size) {
    const float* x   = (const float*)d_in[0];
    const void*  ei  = d_in[1];
    const float* W1  = (const float*)d_in[3];
    const float* b1  = (const float*)d_in[4];
    const float* W2  = (const float*)d_in[5];
    const float* b2  = (const float*)d_in[6];
    float*       out = (float*)d_out;

    const long long nelem = (long long)in_sizes[1];
    const long long E     = nelem / 2;
    const int dhid        = in_sizes[4];         // 512
    const int dout        = in_sizes[6];         // 128
    const int din         = in_sizes[3] / dhid;  // 512
    const int n           = in_sizes[0] / din;   // 100000

    __half *xh_p, *h16_p, *agg16_p, *wt1_p, *wt2_p, *hs2h_p;
    float *dinv_p;
    int *cnt_p, *rowp_p, *cur_p, *col_p, *bsum_p;
    cudaGetSymbolAddress((void**)&xh_p,    g_xh);
    cudaGetSymbolAddress((void**)&h16_p,   g_h16);
    cudaGetSymbolAddress((void**)&agg16_p, g_agg16);
    cudaGetSymbolAddress((void**)&wt1_p,   g_wt1);
    cudaGetSymbolAddress((void**)&wt2_p,   g_wt2);
    cudaGetSymbolAddress((void**)&hs2h_p,  g_hs2h);
    cudaGetSymbolAddress((void**)&dinv_p,  g_dinv);
    cudaGetSymbolAddress((void**)&cnt_p,   g_cnt);
    cudaGetSymbolAddress((void**)&rowp_p,  g_rowp);
    cudaGetSymbolAddress((void**)&cur_p,   g_cur);
    cudaGetSymbolAddress((void**)&col_p,   g_col);
    cudaGetSymbolAddress((void**)&bsum_p,  g_bsum);

    static bool attr_set = false;
    if (!attr_set) {
        cudaFuncSetAttribute(k_gemm_big, cudaFuncAttributeMaxDynamicSharedMemorySize, G1_SMEM);
        attr_set = true;
    }

    const int eb   = (int)((E + 255) / 256);
    const int nb   = (n + 255) / 256;
    const int nblk = (n + 1023) / 1024;
    const int pull_blocks = (int)(((long long)n * 32 + 255) / 256);

    cudaStream_t sB = g_sh.ok ? g_sh.s : (cudaStream_t)0;
    const bool fork = g_sh.ok;

    // ---- fork side stream ----
    if (fork) {
        cudaEventRecord(g_sh.e0, 0);
        cudaStreamWaitEvent(sB, g_sh.e0, 0);
    }

    // stream0 chain (feature): xcvt -> W1^T -> GEMM1
    k_xcvt<<<(MAXN * 64 + 255) / 256, 256>>>(x, n, xh_p);                 // 1
    {
        dim3 grid(dhid / 32, din / 32), blk(32, 8);
        k_transpose_h<<<grid, blk>>>(W1, wt1_p, din, dhid);               // 2
    }
    k_init<<<nb, 256, 0, sB>>>(ei, nelem, n, cnt_p);                      // 3 (B)
    {
        dim3 grid(2, (n + 127) / 128);
        k_gemm_big<<<grid, 512, G1_SMEM>>>(xh_p, wt1_p, h16_p);           // 4 (profiled)
    }

    // streamB chain (graph): hist -> scan -> dinv/cursor -> scatter -> W2^T
    k_hist<<<eb, 256, 0, sB>>>(ei, E, cnt_p);
    k_scan_blk<<<nblk, 1024, 0, sB>>>(cnt_p, rowp_p, bsum_p, n);
    k_scan_top<<<1, 1024, 0, sB>>>(bsum_p, nblk);
    k_scan_add<<<(n + 256) / 256, 256, 0, sB>>>(rowp_p, bsum_p, n, nblk);
    k_dinv_cursor<<<nb, 256, 0, sB>>>(cnt_p, rowp_p, dinv_p, cur_p, n);
    k_scatter<<<eb, 256, 0, sB>>>(ei, E, cur_p, col_p);
    {
        dim3 grid(dout / 32, dhid / 32), blk(32, 8);
        k_transpose_h<<<grid, blk, 0, sB>>>(W2, wt2_p, dhid, dout);
    }

    // ---- join ----
    if (fork) {
        cudaEventRecord(g_sh.e1, sB);
        cudaStreamWaitEvent((cudaStream_t)0, g_sh.e1, 0);
    }

    // layer-1 pull, 4 chunks of 128 feats
    for (int cidx = 0; cidx < 4; cidx++) {
        k_pull1_h<<<pull_blocks, 256>>>(rowp_p, col_p, h16_p, dinv_p,
                                        b1, agg16_p, n, cidx * 32);
    }

    // GEMM2 (fp16 out)
    {
        dim3 grid(1, (n + 127) / 128);
        k_gemm2<<<grid, 256>>>(agg16_p, wt2_p, dinv_p, hs2h_p, n);
    }
    // layer-2 pull
    k_pull2<<<pull_blocks, 256>>>(rowp_p, col_p, hs2h_p, dinv_p, b2, out, n);

    (void)n_in; (void)out_size;
}